// round 4
// baseline (speedup 1.0000x reference)
#include <cuda_runtime.h>
#include <cuda_bf16.h>
#include <math.h>

// Problem constants
#define BB 2
#define TT 2048
#define DD 1024
#define HH 16
#define DH 64
#define WIN 128
#define BT (BB*TT)          // 4096

// ---------------- scratch (device globals; no allocation allowed) ----------
__device__ float g_q[BT * DD];
__device__ float g_k[BT * DD];
__device__ float g_v[BT * DD];
__device__ float g_att[BT * DD];
__device__ float g_cos[TT * 32];
__device__ float g_sin[TT * 32];

// ---------------- RoPE tables (double precision trig, rounded to fp32) -----
__global__ void rope_table_kernel() {
    int idx = blockIdx.x * blockDim.x + threadIdx.x;
    if (idx >= TT * 32) return;
    int t = idx >> 5;
    int i = idx & 31;
    double inv = exp(-log(10000.0) * (double)(2 * i) / 64.0);
    double a = (double)t * inv;
    g_cos[idx] = (float)cos(a);
    g_sin[idx] = (float)sin(a);
}

// ---------------- SGEMM: C[m,n] = sum_k A[m,k]*B[n,k] (+bias[n]) -----------
// A: M x 1024 row-major, B: N x 1024 row-major (i.e. X @ W^T), M=4096, N=1024
#define BM 128
#define BN 128
#define BK 8
#define TM 8
#define TN 8

__device__ __forceinline__ void gemm_body(const float* __restrict__ A,
                                          const float* __restrict__ B,
                                          float* __restrict__ C,
                                          const float* __restrict__ bias) {
    __shared__ float As[BK][BM];
    __shared__ float Bs[BK][BN];

    const int tid = threadIdx.x;
    const int tx = tid & 15;        // 0..15 -> col group
    const int ty = tid >> 4;        // 0..15 -> row group
    const int rowC = blockIdx.y * BM;
    const int colC = blockIdx.x * BN;

    const int lrow = tid >> 1;          // 0..127
    const int lk   = (tid & 1) * 4;     // 0 or 4

    const float* Aptr = A + (size_t)(rowC + lrow) * DD + lk;
    const float* Bptr = B + (size_t)(colC + lrow) * DD + lk;

    float acc[TM][TN];
#pragma unroll
    for (int i = 0; i < TM; i++)
#pragma unroll
        for (int j = 0; j < TN; j++) acc[i][j] = 0.f;

    for (int k0 = 0; k0 < DD; k0 += BK) {
        float4 a4 = *(const float4*)(Aptr + k0);
        float4 b4 = *(const float4*)(Bptr + k0);
        __syncthreads();
        As[lk + 0][lrow] = a4.x; As[lk + 1][lrow] = a4.y;
        As[lk + 2][lrow] = a4.z; As[lk + 3][lrow] = a4.w;
        Bs[lk + 0][lrow] = b4.x; Bs[lk + 1][lrow] = b4.y;
        Bs[lk + 2][lrow] = b4.z; Bs[lk + 3][lrow] = b4.w;
        __syncthreads();
#pragma unroll
        for (int kk = 0; kk < BK; kk++) {
            float a[TM], b[TN];
            float4 av0 = *(const float4*)&As[kk][ty * TM];
            float4 av1 = *(const float4*)&As[kk][ty * TM + 4];
            a[0] = av0.x; a[1] = av0.y; a[2] = av0.z; a[3] = av0.w;
            a[4] = av1.x; a[5] = av1.y; a[6] = av1.z; a[7] = av1.w;
            float4 bv0 = *(const float4*)&Bs[kk][tx * TN];
            float4 bv1 = *(const float4*)&Bs[kk][tx * TN + 4];
            b[0] = bv0.x; b[1] = bv0.y; b[2] = bv0.z; b[3] = bv0.w;
            b[4] = bv1.x; b[5] = bv1.y; b[6] = bv1.z; b[7] = bv1.w;
#pragma unroll
            for (int i = 0; i < TM; i++)
#pragma unroll
                for (int j = 0; j < TN; j++)
                    acc[i][j] = fmaf(a[i], b[j], acc[i][j]);
        }
    }

#pragma unroll
    for (int i = 0; i < TM; i++) {
        int m = rowC + ty * TM + i;
        float* crow = C + (size_t)m * DD + colC + tx * TN;
#pragma unroll
        for (int j4 = 0; j4 < 2; j4++) {
            float4 r;
            int n = colC + tx * TN + j4 * 4;
            float b0 = bias ? bias[n + 0] : 0.f;
            float b1 = bias ? bias[n + 1] : 0.f;
            float b2 = bias ? bias[n + 2] : 0.f;
            float b3 = bias ? bias[n + 3] : 0.f;
            r.x = acc[i][j4 * 4 + 0] + b0;
            r.y = acc[i][j4 * 4 + 1] + b1;
            r.z = acc[i][j4 * 4 + 2] + b2;
            r.w = acc[i][j4 * 4 + 3] + b3;
            *(float4*)(crow + j4 * 4) = r;
        }
    }
}

__global__ void __launch_bounds__(256) sgemm_qkv_kernel(const float* __restrict__ X,
                                                        const float* __restrict__ Wq,
                                                        const float* __restrict__ Wk,
                                                        const float* __restrict__ Wv) {
    const float* W = (blockIdx.z == 0) ? Wq : (blockIdx.z == 1) ? Wk : Wv;
    float* out = (blockIdx.z == 0) ? g_q : (blockIdx.z == 1) ? g_k : g_v;
    gemm_body(X, W, out, nullptr);
}

__global__ void __launch_bounds__(256) sgemm_out_kernel(const float* __restrict__ Wo,
                                                        const float* __restrict__ bo,
                                                        float* __restrict__ out) {
    gemm_body(g_att, Wo, out, bo);
}

// ---------------- RoPE apply (q and k, in place) ---------------------------
__global__ void rope_apply_kernel() {
    int idx = blockIdx.x * blockDim.x + threadIdx.x;
    if (idx >= BT * HH * 32) return;
    int bt = idx >> 9;          // /512
    int r = idx & 511;
    int h = r >> 5;
    int i = r & 31;
    int t = bt & (TT - 1);
    float c = g_cos[t * 32 + i];
    float s = g_sin[t * 32 + i];
    int base = bt * DD + h * DH + i;
    float q0 = g_q[base], q1 = g_q[base + 32];
    g_q[base]      = q0 * c - q1 * s;
    g_q[base + 32] = q1 * c + q0 * s;
    float k0 = g_k[base], k1 = g_k[base + 32];
    g_k[base]      = k0 * c - k1 * s;
    g_k[base + 32] = k1 * c + k0 * s;
}

// ---------------- sliding-window attention ---------------------------------
// CTA = (q-tile of 64, head, batch). Keys window: [q0-127, q0+63] -> <=191.
// NOTE: writes g_att directly from device code. Passing a __device__ global's
// address from host code (previous round's bug) passes the HOST shadow-symbol
// address, not the device address — the kernel wrote through garbage and
// g_att stayed zero (out == bo, rel_err 0.998).
#define QT 64
#define KTM 192
#define AT_THREADS 256
#define ATT_SMEM_FLOATS (64*KTM + KTM*64 + QT*(KTM+1) + QT*64)
#define ATT_SMEM_BYTES (ATT_SMEM_FLOATS * 4)

__global__ void __launch_bounds__(AT_THREADS) attn_kernel() {
    extern __shared__ float sm[];
    float* sKt = sm;                       // [64][KTM]  (dim-major, key consecutive)
    float* sV  = sKt + 64 * KTM;           // [KTM][64]
    float* sS  = sV + KTM * 64;            // [QT][KTM+1]
    float* sQ  = sS + QT * (KTM + 1);      // [QT][64]

    const int b = blockIdx.z, h = blockIdx.y;
    const int q0 = blockIdx.x * QT;
    const int tid = threadIdx.x;
    const int kmin = max(0, q0 - (WIN - 1));
    const int numK = q0 + QT - kmin;       // <= 191
    const int hoff = h * DH;

    const float* kbase = g_k + (size_t)(b * TT + kmin) * DD + hoff;
    const float* vbase = g_v + (size_t)(b * TT + kmin) * DD + hoff;
    const float* qbase = g_q + (size_t)(b * TT + q0) * DD + hoff;

    // load K (transposed) and V
    for (int e = tid; e < numK * 16; e += AT_THREADS) {
        int jl = e >> 4;
        int dq = (e & 15) * 4;
        float4 kv = *(const float4*)(kbase + (size_t)jl * DD + dq);
        sKt[(dq + 0) * KTM + jl] = kv.x;
        sKt[(dq + 1) * KTM + jl] = kv.y;
        sKt[(dq + 2) * KTM + jl] = kv.z;
        sKt[(dq + 3) * KTM + jl] = kv.w;
        float4 vv = *(const float4*)(vbase + (size_t)jl * DD + dq);
        *(float4*)&sV[jl * 64 + dq] = vv;
    }
    // load Q
    for (int e = tid; e < QT * 16; e += AT_THREADS) {
        int qi = e >> 4;
        int dq = (e & 15) * 4;
        *(float4*)&sQ[qi * 64 + dq] = *(const float4*)(qbase + (size_t)qi * DD + dq);
    }
    __syncthreads();

    // scores + softmax: warp w handles queries w*8 .. w*8+7, 4 at a time
    const int warp = tid >> 5, lane = tid & 31;
    const float sm_scale = 0.125f;   // 1/sqrt(64)

#pragma unroll
    for (int rg = 0; rg < 2; rg++) {
        const int qib = warp * 8 + rg * 4;
        float sc[6][4];
#pragma unroll
        for (int m = 0; m < 6; m++) {
            int kl = lane + 32 * m;
            float a0 = 0.f, a1 = 0.f, a2 = 0.f, a3 = 0.f;
            if (kl < numK) {
#pragma unroll
                for (int d0 = 0; d0 < 64; d0 += 4) {
                    float kv0 = sKt[(d0 + 0) * KTM + kl];
                    float kv1 = sKt[(d0 + 1) * KTM + kl];
                    float kv2 = sKt[(d0 + 2) * KTM + kl];
                    float kv3 = sKt[(d0 + 3) * KTM + kl];
                    float4 qv0 = *(const float4*)&sQ[(qib + 0) * 64 + d0];
                    float4 qv1 = *(const float4*)&sQ[(qib + 1) * 64 + d0];
                    float4 qv2 = *(const float4*)&sQ[(qib + 2) * 64 + d0];
                    float4 qv3 = *(const float4*)&sQ[(qib + 3) * 64 + d0];
                    a0 = fmaf(qv0.x, kv0, a0); a0 = fmaf(qv0.y, kv1, a0);
                    a0 = fmaf(qv0.z, kv2, a0); a0 = fmaf(qv0.w, kv3, a0);
                    a1 = fmaf(qv1.x, kv0, a1); a1 = fmaf(qv1.y, kv1, a1);
                    a1 = fmaf(qv1.z, kv2, a1); a1 = fmaf(qv1.w, kv3, a1);
                    a2 = fmaf(qv2.x, kv0, a2); a2 = fmaf(qv2.y, kv1, a2);
                    a2 = fmaf(qv2.z, kv2, a2); a2 = fmaf(qv2.w, kv3, a2);
                    a3 = fmaf(qv3.x, kv0, a3); a3 = fmaf(qv3.y, kv1, a3);
                    a3 = fmaf(qv3.z, kv2, a3); a3 = fmaf(qv3.w, kv3, a3);
                }
            }
            sc[m][0] = a0; sc[m][1] = a1; sc[m][2] = a2; sc[m][3] = a3;
        }
        // per-query softmax
#pragma unroll
        for (int j = 0; j < 4; j++) {
            int qg = q0 + qib + j;
            int lo = max(0, qg - (WIN - 1)) - kmin;
            int hi = qg - kmin;
            float mx = -1e30f;
#pragma unroll
            for (int m = 0; m < 6; m++) {
                int kl = lane + 32 * m;
                float s = (kl >= lo && kl <= hi) ? sc[m][j] * sm_scale : -1e30f;
                sc[m][j] = s;
                mx = fmaxf(mx, s);
            }
#pragma unroll
            for (int off = 16; off > 0; off >>= 1)
                mx = fmaxf(mx, __shfl_xor_sync(0xffffffffu, mx, off));
            float ssum = 0.f;
#pragma unroll
            for (int m = 0; m < 6; m++) {
                float e = __expf(sc[m][j] - mx);
                sc[m][j] = e;
                ssum += e;
            }
#pragma unroll
            for (int off = 16; off > 0; off >>= 1)
                ssum += __shfl_xor_sync(0xffffffffu, ssum, off);
            float inv = __frcp_rn(ssum);
#pragma unroll
            for (int m = 0; m < 6; m++) {
                int kl = lane + 32 * m;
                sS[(qib + j) * (KTM + 1) + kl] = sc[m][j] * inv;
            }
        }
    }
    __syncthreads();

    // PV: thread -> (query qi = tid/4, dim segment of 16)
    {
        const int qi = tid >> 2;
        const int ds = (tid & 3) * 16;
        float acc[16];
#pragma unroll
        for (int i = 0; i < 16; i++) acc[i] = 0.f;
        const float* srow = &sS[qi * (KTM + 1)];
#pragma unroll 2
        for (int kl = 0; kl < numK; kl++) {
            float p = srow[kl];
            const float* vr = &sV[kl * 64 + ds];
#pragma unroll
            for (int i = 0; i < 4; i++) {
                float4 vv = *(const float4*)(vr + i * 4);
                acc[i * 4 + 0] = fmaf(p, vv.x, acc[i * 4 + 0]);
                acc[i * 4 + 1] = fmaf(p, vv.y, acc[i * 4 + 1]);
                acc[i * 4 + 2] = fmaf(p, vv.z, acc[i * 4 + 2]);
                acc[i * 4 + 3] = fmaf(p, vv.w, acc[i * 4 + 3]);
            }
        }
        // write g_att via the DEVICE-side symbol (correct address)
        float* orow = g_att + (size_t)(b * TT + q0 + qi) * DD + hoff + ds;
#pragma unroll
        for (int i = 0; i < 4; i++) {
            float4 r;
            r.x = acc[i * 4 + 0]; r.y = acc[i * 4 + 1];
            r.z = acc[i * 4 + 2]; r.w = acc[i * 4 + 3];
            *(float4*)(orow + i * 4) = r;
        }
    }
}

// ---------------- launch ----------------------------------------------------
extern "C" void kernel_launch(void* const* d_in, const int* in_sizes, int n_in,
                              void* d_out, int out_size) {
    const float* x  = (const float*)d_in[0];
    const float* Wq = (const float*)d_in[1];
    const float* Wk = (const float*)d_in[2];
    const float* Wv = (const float*)d_in[3];
    const float* Wo = (const float*)d_in[4];
    const float* bo = (const float*)d_in[5];
    float* out = (float*)d_out;

    cudaFuncSetAttribute(attn_kernel, cudaFuncAttributeMaxDynamicSharedMemorySize,
                         ATT_SMEM_BYTES);

    rope_table_kernel<<<(TT * 32 + 255) / 256, 256>>>();

    dim3 gqkv(DD / BN, BT / BM, 3);
    sgemm_qkv_kernel<<<gqkv, 256>>>(x, Wq, Wk, Wv);

    rope_apply_kernel<<<(BT * HH * 32 + 255) / 256, 256>>>();

    attn_kernel<<<dim3(TT / QT, HH, BB), AT_THREADS, ATT_SMEM_BYTES>>>();

    dim3 go(DD / BN, BT / BM, 1);
    sgemm_out_kernel<<<go, 256>>>(Wo, bo, out);
}

// round 5
// speedup vs baseline: 3.0412x; 3.0412x over previous
#include <cuda_runtime.h>
#include <cuda_bf16.h>
#include <math.h>
#include <stdint.h>

// Problem constants
#define BB 2
#define TT 2048
#define DD 1024
#define HH 16
#define DH 64
#define WIN 128
#define BT (BB*TT)          // 4096

// ---------------- scratch (device globals; no allocation allowed) ----------
__device__ float g_q[BT * DD];
__device__ float g_k[BT * DD];
__device__ float g_v[BT * DD];
__device__ float g_att[BT * DD];
__device__ float g_cos[TT * 32];
__device__ float g_sin[TT * 32];

// bf16 hi/lo split operands for tensor-core GEMMs
__device__ __nv_bfloat16 g_xh[BT * DD];
__device__ __nv_bfloat16 g_xl[BT * DD];
__device__ __nv_bfloat16 g_wh[4][DD * DD];
__device__ __nv_bfloat16 g_wl[4][DD * DD];
__device__ __nv_bfloat16 g_ah[BT * DD];
__device__ __nv_bfloat16 g_al[BT * DD];

// ---------------- RoPE tables (double precision trig, rounded to fp32) -----
__global__ void rope_table_kernel() {
    int idx = blockIdx.x * blockDim.x + threadIdx.x;
    if (idx >= TT * 32) return;
    int t = idx >> 5;
    int i = idx & 31;
    double inv = exp(-log(10000.0) * (double)(2 * i) / 64.0);
    double a = (double)t * inv;
    g_cos[idx] = (float)cos(a);
    g_sin[idx] = (float)sin(a);
}

// ---------------- fp32 -> bf16 hi/lo split conversions ---------------------
__device__ __forceinline__ void split2(float x, __nv_bfloat16& h, __nv_bfloat16& l) {
    h = __float2bfloat16(x);
    l = __float2bfloat16(x - __bfloat162float(h));
}

__global__ void cvt_x_kernel(const float* __restrict__ src) {
    int i = blockIdx.x * blockDim.x + threadIdx.x;      // float4 index
    if (i >= BT * DD / 4) return;
    float4 v = ((const float4*)src)[i];
    __nv_bfloat16 h0,h1,h2,h3,l0,l1,l2,l3;
    split2(v.x,h0,l0); split2(v.y,h1,l1); split2(v.z,h2,l2); split2(v.w,h3,l3);
    ((__nv_bfloat162*)g_xh)[i*2+0] = __nv_bfloat162{h0,h1};
    ((__nv_bfloat162*)g_xh)[i*2+1] = __nv_bfloat162{h2,h3};
    ((__nv_bfloat162*)g_xl)[i*2+0] = __nv_bfloat162{l0,l1};
    ((__nv_bfloat162*)g_xl)[i*2+1] = __nv_bfloat162{l2,l3};
}

__global__ void cvt_w_kernel(const float* __restrict__ src, int which) {
    int i = blockIdx.x * blockDim.x + threadIdx.x;
    if (i >= DD * DD / 4) return;
    float4 v = ((const float4*)src)[i];
    __nv_bfloat16 h0,h1,h2,h3,l0,l1,l2,l3;
    split2(v.x,h0,l0); split2(v.y,h1,l1); split2(v.z,h2,l2); split2(v.w,h3,l3);
    ((__nv_bfloat162*)g_wh[which])[i*2+0] = __nv_bfloat162{h0,h1};
    ((__nv_bfloat162*)g_wh[which])[i*2+1] = __nv_bfloat162{h2,h3};
    ((__nv_bfloat162*)g_wl[which])[i*2+0] = __nv_bfloat162{l0,l1};
    ((__nv_bfloat162*)g_wl[which])[i*2+1] = __nv_bfloat162{l2,l3};
}

__global__ void cvt_att_kernel() {
    int i = blockIdx.x * blockDim.x + threadIdx.x;
    if (i >= BT * DD / 4) return;
    float4 v = ((const float4*)g_att)[i];
    __nv_bfloat16 h0,h1,h2,h3,l0,l1,l2,l3;
    split2(v.x,h0,l0); split2(v.y,h1,l1); split2(v.z,h2,l2); split2(v.w,h3,l3);
    ((__nv_bfloat162*)g_ah)[i*2+0] = __nv_bfloat162{h0,h1};
    ((__nv_bfloat162*)g_ah)[i*2+1] = __nv_bfloat162{h2,h3};
    ((__nv_bfloat162*)g_al)[i*2+0] = __nv_bfloat162{l0,l1};
    ((__nv_bfloat162*)g_al)[i*2+1] = __nv_bfloat162{l2,l3};
}

// ---------------- tensor-core GEMM (bf16 hi/lo split, fp32 accumulate) -----
// C[m,n] = sum_k A[m,k]*B[n,k] (+bias[n])
// CTA tile 128x128, K-chunk 32, 256 threads = 8 warps (2x4), warp tile 64x32.
// SMEM per stage: Ah,Al,Bh,Bl each 128 rows x 40 bf16 (pad 32->40 for
// conflict-free ldmatrix). 2 stages, cp.async pipelined.

#define GK_CHUNK 32
#define GPAD 40                         // padded row length in bf16
#define G_ARR_BYTES (128 * GPAD * 2)    // 10240
#define G_STAGE_BYTES (4 * G_ARR_BYTES) // 40960
#define G_SMEM_BYTES (2 * G_STAGE_BYTES)

__device__ __forceinline__ void cp16(uint32_t dst, const void* src) {
    asm volatile("cp.async.cg.shared.global [%0], [%1], 16;\n" :: "r"(dst), "l"(src));
}
__device__ __forceinline__ void ldsm_x4(uint32_t* r, uint32_t a) {
    asm volatile("ldmatrix.sync.aligned.m8n8.x4.shared.b16 {%0,%1,%2,%3}, [%4];\n"
                 : "=r"(r[0]), "=r"(r[1]), "=r"(r[2]), "=r"(r[3]) : "r"(a));
}
__device__ __forceinline__ void ldsm_x2(uint32_t* r, uint32_t a) {
    asm volatile("ldmatrix.sync.aligned.m8n8.x2.shared.b16 {%0,%1}, [%2];\n"
                 : "=r"(r[0]), "=r"(r[1]) : "r"(a));
}
__device__ __forceinline__ void mma16816(float* c, const uint32_t* a, const uint32_t* b) {
    asm volatile("mma.sync.aligned.m16n8k16.row.col.f32.bf16.bf16.f32 "
                 "{%0,%1,%2,%3}, {%4,%5,%6,%7}, {%8,%9}, {%0,%1,%2,%3};\n"
                 : "+f"(c[0]), "+f"(c[1]), "+f"(c[2]), "+f"(c[3])
                 : "r"(a[0]), "r"(a[1]), "r"(a[2]), "r"(a[3]), "r"(b[0]), "r"(b[1]));
}

__device__ __forceinline__ void mma_gemm_body(
    const __nv_bfloat16* __restrict__ Ah, const __nv_bfloat16* __restrict__ Al,
    const __nv_bfloat16* __restrict__ Bh, const __nv_bfloat16* __restrict__ Bl,
    float* __restrict__ C, const float* __restrict__ bias)
{
    extern __shared__ char smem_raw[];
    const int tid = threadIdx.x;
    const int lane = tid & 31;
    const int wid = tid >> 5;
    const int bM = blockIdx.y * 128;
    const int bN = blockIdx.x * 128;
    const int wM = (wid >> 2) * 64;
    const int wN = (wid & 3) * 32;

    const uint32_t smem_base = (uint32_t)__cvta_generic_to_shared(smem_raw);

    // loader mapping: 64 rows per pass (4 threads x 16B cover 32 bf16 row)
    const int ldr = tid >> 2;           // 0..63
    const int ldc = (tid & 3) * 8;      // bf16 element offset

    const __nv_bfloat16* pAh = Ah + (size_t)(bM + ldr) * DD + ldc;
    const __nv_bfloat16* pAl = Al + (size_t)(bM + ldr) * DD + ldc;
    const __nv_bfloat16* pBh = Bh + (size_t)(bN + ldr) * DD + ldc;
    const __nv_bfloat16* pBl = Bl + (size_t)(bN + ldr) * DD + ldc;

    const uint32_t dbase = smem_base + ldr * (GPAD * 2) + ldc * 2;
    const uint32_t rowhalf = 64 * GPAD * 2;   // bytes for 64 rows

    float acc[4][4][4];
#pragma unroll
    for (int mi = 0; mi < 4; mi++)
#pragma unroll
        for (int ni = 0; ni < 4; ni++)
#pragma unroll
            for (int r = 0; r < 4; r++) acc[mi][ni][r] = 0.f;

    auto issue = [&](int buf, int k0) {
        uint32_t d = dbase + buf * G_STAGE_BYTES;
        cp16(d,                              pAh + k0);
        cp16(d + rowhalf,                    pAh + 64 * DD + k0);
        cp16(d + G_ARR_BYTES,                pAl + k0);
        cp16(d + G_ARR_BYTES + rowhalf,      pAl + 64 * DD + k0);
        cp16(d + 2 * G_ARR_BYTES,            pBh + k0);
        cp16(d + 2 * G_ARR_BYTES + rowhalf,  pBh + 64 * DD + k0);
        cp16(d + 3 * G_ARR_BYTES,            pBl + k0);
        cp16(d + 3 * G_ARR_BYTES + rowhalf,  pBl + 64 * DD + k0);
        asm volatile("cp.async.commit_group;\n");
    };

    issue(0, 0);
    const int NCH = DD / GK_CHUNK;   // 32
    for (int c = 0; c < NCH; c++) {
        if (c + 1 < NCH) {
            issue((c + 1) & 1, (c + 1) * GK_CHUNK);
            asm volatile("cp.async.wait_group 1;\n");
        } else {
            asm volatile("cp.async.wait_group 0;\n");
        }
        __syncthreads();

        uint32_t sb = smem_base + (c & 1) * G_STAGE_BYTES;
#pragma unroll
        for (int kh = 0; kh < 2; kh++) {
            uint32_t ah[4][4], al[4][4];
            const int arow = wM + (lane & 15);
            const int acol = kh * 16 + ((lane >> 4) << 3);
#pragma unroll
            for (int mi = 0; mi < 4; mi++) {
                uint32_t addr = sb + (uint32_t)((arow + mi * 16) * (GPAD * 2) + acol * 2);
                ldsm_x4(ah[mi], addr);
                ldsm_x4(al[mi], addr + G_ARR_BYTES);
            }
            const int brow = wN + (lane & 7);
            const int bcol = kh * 16 + ((lane >> 3) & 1) * 8;
#pragma unroll
            for (int ni = 0; ni < 4; ni++) {
                uint32_t baddr = sb + 2 * G_ARR_BYTES +
                                 (uint32_t)((brow + ni * 8) * (GPAD * 2) + bcol * 2);
                uint32_t bh[2], bl[2];
                ldsm_x2(bh, baddr);
                ldsm_x2(bl, baddr + G_ARR_BYTES);
#pragma unroll
                for (int mi = 0; mi < 4; mi++) {
                    mma16816(acc[mi][ni], ah[mi], bh);   // hi*hi
                    mma16816(acc[mi][ni], ah[mi], bl);   // hi*lo
                    mma16816(acc[mi][ni], al[mi], bh);   // lo*hi
                }
            }
        }
        __syncthreads();
    }

    // epilogue
#pragma unroll
    for (int mi = 0; mi < 4; mi++) {
        int m0 = bM + wM + mi * 16 + (lane >> 2);
#pragma unroll
        for (int ni = 0; ni < 4; ni++) {
            int n = bN + wN + ni * 8 + (lane & 3) * 2;
            float b0 = 0.f, b1 = 0.f;
            if (bias) { b0 = bias[n]; b1 = bias[n + 1]; }
            float2 r0; r0.x = acc[mi][ni][0] + b0; r0.y = acc[mi][ni][1] + b1;
            float2 r1; r1.x = acc[mi][ni][2] + b0; r1.y = acc[mi][ni][3] + b1;
            *(float2*)&C[(size_t)m0 * DD + n]       = r0;
            *(float2*)&C[(size_t)(m0 + 8) * DD + n] = r1;
        }
    }
}

__global__ void __launch_bounds__(256) qkv_mma_kernel() {
    int z = blockIdx.z;
    float* C = (z == 0) ? g_q : (z == 1) ? g_k : g_v;
    mma_gemm_body(g_xh, g_xl, g_wh[z], g_wl[z], C, nullptr);
}

__global__ void __launch_bounds__(256) out_mma_kernel(const float* __restrict__ bo,
                                                      float* __restrict__ out) {
    mma_gemm_body(g_ah, g_al, g_wh[3], g_wl[3], out, bo);
}

// ---------------- RoPE apply (q and k, in place) ---------------------------
__global__ void rope_apply_kernel() {
    int idx = blockIdx.x * blockDim.x + threadIdx.x;
    if (idx >= BT * HH * 32) return;
    int bt = idx >> 9;
    int r = idx & 511;
    int h = r >> 5;
    int i = r & 31;
    int t = bt & (TT - 1);
    float c = g_cos[t * 32 + i];
    float s = g_sin[t * 32 + i];
    int base = bt * DD + h * DH + i;
    float q0 = g_q[base], q1 = g_q[base + 32];
    g_q[base]      = q0 * c - q1 * s;
    g_q[base + 32] = q1 * c + q0 * s;
    float k0 = g_k[base], k1 = g_k[base + 32];
    g_k[base]      = k0 * c - k1 * s;
    g_k[base + 32] = k1 * c + k0 * s;
}

// ---------------- sliding-window attention ---------------------------------
#define QT 64
#define KTM 192
#define AT_THREADS 256
#define ATT_SMEM_FLOATS (64*KTM + KTM*64 + QT*(KTM+1) + QT*64)
#define ATT_SMEM_BYTES (ATT_SMEM_FLOATS * 4)

__global__ void __launch_bounds__(AT_THREADS) attn_kernel() {
    extern __shared__ float sm[];
    float* sKt = sm;                       // [64][KTM]
    float* sV  = sKt + 64 * KTM;           // [KTM][64]
    float* sS  = sV + KTM * 64;            // [QT][KTM+1]
    float* sQ  = sS + QT * (KTM + 1);      // [QT][64]

    const int b = blockIdx.z, h = blockIdx.y;
    const int q0 = blockIdx.x * QT;
    const int tid = threadIdx.x;
    const int kmin = max(0, q0 - (WIN - 1));
    const int numK = q0 + QT - kmin;       // <= 191
    const int hoff = h * DH;

    const float* kbase = g_k + (size_t)(b * TT + kmin) * DD + hoff;
    const float* vbase = g_v + (size_t)(b * TT + kmin) * DD + hoff;
    const float* qbase = g_q + (size_t)(b * TT + q0) * DD + hoff;

    for (int e = tid; e < numK * 16; e += AT_THREADS) {
        int jl = e >> 4;
        int dq = (e & 15) * 4;
        float4 kv = *(const float4*)(kbase + (size_t)jl * DD + dq);
        sKt[(dq + 0) * KTM + jl] = kv.x;
        sKt[(dq + 1) * KTM + jl] = kv.y;
        sKt[(dq + 2) * KTM + jl] = kv.z;
        sKt[(dq + 3) * KTM + jl] = kv.w;
        float4 vv = *(const float4*)(vbase + (size_t)jl * DD + dq);
        *(float4*)&sV[jl * 64 + dq] = vv;
    }
    for (int e = tid; e < QT * 16; e += AT_THREADS) {
        int qi = e >> 4;
        int dq = (e & 15) * 4;
        *(float4*)&sQ[qi * 64 + dq] = *(const float4*)(qbase + (size_t)qi * DD + dq);
    }
    __syncthreads();

    const int warp = tid >> 5, lane = tid & 31;
    const float sm_scale = 0.125f;

#pragma unroll
    for (int rg = 0; rg < 2; rg++) {
        const int qib = warp * 8 + rg * 4;
        float sc[6][4];
#pragma unroll
        for (int m = 0; m < 6; m++)
#pragma unroll
            for (int j = 0; j < 4; j++) sc[m][j] = 0.f;

        // d-chunk outer: hold 4 queries x 8 dims in regs, reuse across 6 key groups
        for (int dc = 0; dc < 64; dc += 8) {
            float4 qv[4][2];
#pragma unroll
            for (int j = 0; j < 4; j++) {
                qv[j][0] = *(const float4*)&sQ[(qib + j) * 64 + dc];
                qv[j][1] = *(const float4*)&sQ[(qib + j) * 64 + dc + 4];
            }
#pragma unroll
            for (int m = 0; m < 6; m++) {
                int kl = lane + 32 * m;
                if (kl < numK) {
                    float kv[8];
#pragma unroll
                    for (int hh = 0; hh < 8; hh++)
                        kv[hh] = sKt[(dc + hh) * KTM + kl];
#pragma unroll
                    for (int j = 0; j < 4; j++) {
                        float a = sc[m][j];
                        a = fmaf(qv[j][0].x, kv[0], a);
                        a = fmaf(qv[j][0].y, kv[1], a);
                        a = fmaf(qv[j][0].z, kv[2], a);
                        a = fmaf(qv[j][0].w, kv[3], a);
                        a = fmaf(qv[j][1].x, kv[4], a);
                        a = fmaf(qv[j][1].y, kv[5], a);
                        a = fmaf(qv[j][1].z, kv[6], a);
                        a = fmaf(qv[j][1].w, kv[7], a);
                        sc[m][j] = a;
                    }
                }
            }
        }

        // per-query softmax
#pragma unroll
        for (int j = 0; j < 4; j++) {
            int qg = q0 + qib + j;
            int lo = max(0, qg - (WIN - 1)) - kmin;
            int hi = qg - kmin;
            float mx = -1e30f;
#pragma unroll
            for (int m = 0; m < 6; m++) {
                int kl = lane + 32 * m;
                float s = (kl >= lo && kl <= hi) ? sc[m][j] * sm_scale : -1e30f;
                sc[m][j] = s;
                mx = fmaxf(mx, s);
            }
#pragma unroll
            for (int off = 16; off > 0; off >>= 1)
                mx = fmaxf(mx, __shfl_xor_sync(0xffffffffu, mx, off));
            float ssum = 0.f;
#pragma unroll
            for (int m = 0; m < 6; m++) {
                float e = __expf(sc[m][j] - mx);
                sc[m][j] = e;
                ssum += e;
            }
#pragma unroll
            for (int off = 16; off > 0; off >>= 1)
                ssum += __shfl_xor_sync(0xffffffffu, ssum, off);
            float inv = __frcp_rn(ssum);
#pragma unroll
            for (int m = 0; m < 6; m++) {
                int kl = lane + 32 * m;
                sS[(qib + j) * (KTM + 1) + kl] = sc[m][j] * inv;
            }
        }
    }
    __syncthreads();

    // PV
    {
        const int qi = tid >> 2;
        const int ds = (tid & 3) * 16;
        float acc[16];
#pragma unroll
        for (int i = 0; i < 16; i++) acc[i] = 0.f;
        const float* srow = &sS[qi * (KTM + 1)];
#pragma unroll 2
        for (int kl = 0; kl < numK; kl++) {
            float p = srow[kl];
            const float* vr = &sV[kl * 64 + ds];
#pragma unroll
            for (int i = 0; i < 4; i++) {
                float4 vv = *(const float4*)(vr + i * 4);
                acc[i * 4 + 0] = fmaf(p, vv.x, acc[i * 4 + 0]);
                acc[i * 4 + 1] = fmaf(p, vv.y, acc[i * 4 + 1]);
                acc[i * 4 + 2] = fmaf(p, vv.z, acc[i * 4 + 2]);
                acc[i * 4 + 3] = fmaf(p, vv.w, acc[i * 4 + 3]);
            }
        }
        float* orow = g_att + (size_t)(b * TT + q0 + qi) * DD + hoff + ds;
#pragma unroll
        for (int i = 0; i < 4; i++) {
            float4 r;
            r.x = acc[i * 4 + 0]; r.y = acc[i * 4 + 1];
            r.z = acc[i * 4 + 2]; r.w = acc[i * 4 + 3];
            *(float4*)(orow + i * 4) = r;
        }
    }
}

// ---------------- launch ----------------------------------------------------
extern "C" void kernel_launch(void* const* d_in, const int* in_sizes, int n_in,
                              void* d_out, int out_size) {
    const float* x  = (const float*)d_in[0];
    const float* Wq = (const float*)d_in[1];
    const float* Wk = (const float*)d_in[2];
    const float* Wv = (const float*)d_in[3];
    const float* Wo = (const float*)d_in[4];
    const float* bo = (const float*)d_in[5];
    float* out = (float*)d_out;

    cudaFuncSetAttribute(attn_kernel, cudaFuncAttributeMaxDynamicSharedMemorySize,
                         ATT_SMEM_BYTES);
    cudaFuncSetAttribute(qkv_mma_kernel, cudaFuncAttributeMaxDynamicSharedMemorySize,
                         G_SMEM_BYTES);
    cudaFuncSetAttribute(out_mma_kernel, cudaFuncAttributeMaxDynamicSharedMemorySize,
                         G_SMEM_BYTES);

    rope_table_kernel<<<(TT * 32 + 255) / 256, 256>>>();

    // conversions
    cvt_x_kernel<<<(BT * DD / 4 + 255) / 256, 256>>>(x);
    cvt_w_kernel<<<(DD * DD / 4 + 255) / 256, 256>>>(Wq, 0);
    cvt_w_kernel<<<(DD * DD / 4 + 255) / 256, 256>>>(Wk, 1);
    cvt_w_kernel<<<(DD * DD / 4 + 255) / 256, 256>>>(Wv, 2);
    cvt_w_kernel<<<(DD * DD / 4 + 255) / 256, 256>>>(Wo, 3);

    // QKV projections (tensor cores)
    dim3 gqkv(DD / 128, BT / 128, 3);
    qkv_mma_kernel<<<gqkv, 256, G_SMEM_BYTES>>>();

    rope_apply_kernel<<<(BT * HH * 32 + 255) / 256, 256>>>();

    attn_kernel<<<dim3(TT / QT, HH, BB), AT_THREADS, ATT_SMEM_BYTES>>>();

    cvt_att_kernel<<<(BT * DD / 4 + 255) / 256, 256>>>();

    dim3 go(DD / 128, BT / 128, 1);
    out_mma_kernel<<<go, 256, G_SMEM_BYTES>>>(bo, out);
}

// round 6
// speedup vs baseline: 4.5346x; 1.4910x over previous
#include <cuda_runtime.h>
#include <cuda_bf16.h>
#include <math.h>
#include <stdint.h>

// Problem constants
#define BB 2
#define TT 2048
#define DD 1024
#define HH 16
#define DH 64
#define WIN 128
#define BT (BB*TT)          // 4096

// ---------------- scratch (device globals; no allocation allowed) ----------
__device__ float g_q[BT * DD];
__device__ float g_k[BT * DD];
__device__ float g_v[BT * DD];
__device__ float g_cos[TT * 32];
__device__ float g_sin[TT * 32];

// bf16 hi/lo split operands for tensor-core GEMMs
__device__ __nv_bfloat16 g_xh[BT * DD];
__device__ __nv_bfloat16 g_xl[BT * DD];
__device__ __nv_bfloat16 g_wh[4][DD * DD];
__device__ __nv_bfloat16 g_wl[4][DD * DD];
__device__ __nv_bfloat16 g_ah[BT * DD];   // attention output, hi part
__device__ __nv_bfloat16 g_al[BT * DD];   // attention output, lo part

// ---------------- RoPE tables ----------------------------------------------
__global__ void rope_table_kernel() {
    int idx = blockIdx.x * blockDim.x + threadIdx.x;
    if (idx >= TT * 32) return;
    int t = idx >> 5;
    int i = idx & 31;
    double inv = exp(-log(10000.0) * (double)(2 * i) / 64.0);
    double a = (double)t * inv;
    g_cos[idx] = (float)cos(a);
    g_sin[idx] = (float)sin(a);
}

// ---------------- fp32 -> bf16 hi/lo split conversions ---------------------
__device__ __forceinline__ void split2(float x, __nv_bfloat16& h, __nv_bfloat16& l) {
    h = __float2bfloat16(x);
    l = __float2bfloat16(x - __bfloat162float(h));
}

__global__ void cvt_x_kernel(const float* __restrict__ src) {
    int i = blockIdx.x * blockDim.x + threadIdx.x;
    if (i >= BT * DD / 4) return;
    float4 v = ((const float4*)src)[i];
    __nv_bfloat16 h0,h1,h2,h3,l0,l1,l2,l3;
    split2(v.x,h0,l0); split2(v.y,h1,l1); split2(v.z,h2,l2); split2(v.w,h3,l3);
    ((__nv_bfloat162*)g_xh)[i*2+0] = __nv_bfloat162{h0,h1};
    ((__nv_bfloat162*)g_xh)[i*2+1] = __nv_bfloat162{h2,h3};
    ((__nv_bfloat162*)g_xl)[i*2+0] = __nv_bfloat162{l0,l1};
    ((__nv_bfloat162*)g_xl)[i*2+1] = __nv_bfloat162{l2,l3};
}

__global__ void cvt_w_kernel(const float* __restrict__ src, int which) {
    int i = blockIdx.x * blockDim.x + threadIdx.x;
    if (i >= DD * DD / 4) return;
    float4 v = ((const float4*)src)[i];
    __nv_bfloat16 h0,h1,h2,h3,l0,l1,l2,l3;
    split2(v.x,h0,l0); split2(v.y,h1,l1); split2(v.z,h2,l2); split2(v.w,h3,l3);
    ((__nv_bfloat162*)g_wh[which])[i*2+0] = __nv_bfloat162{h0,h1};
    ((__nv_bfloat162*)g_wh[which])[i*2+1] = __nv_bfloat162{h2,h3};
    ((__nv_bfloat162*)g_wl[which])[i*2+0] = __nv_bfloat162{l0,l1};
    ((__nv_bfloat162*)g_wl[which])[i*2+1] = __nv_bfloat162{l2,l3};
}

// ---------------- mma helpers ----------------------------------------------
__device__ __forceinline__ void cp16(uint32_t dst, const void* src) {
    asm volatile("cp.async.cg.shared.global [%0], [%1], 16;\n" :: "r"(dst), "l"(src));
}
__device__ __forceinline__ void ldsm_x4(uint32_t* r, uint32_t a) {
    asm volatile("ldmatrix.sync.aligned.m8n8.x4.shared.b16 {%0,%1,%2,%3}, [%4];\n"
                 : "=r"(r[0]), "=r"(r[1]), "=r"(r[2]), "=r"(r[3]) : "r"(a));
}
__device__ __forceinline__ void ldsm_x2(uint32_t* r, uint32_t a) {
    asm volatile("ldmatrix.sync.aligned.m8n8.x2.shared.b16 {%0,%1}, [%2];\n"
                 : "=r"(r[0]), "=r"(r[1]) : "r"(a));
}
__device__ __forceinline__ void mma16816(float* c, const uint32_t* a, const uint32_t* b) {
    asm volatile("mma.sync.aligned.m16n8k16.row.col.f32.bf16.bf16.f32 "
                 "{%0,%1,%2,%3}, {%4,%5,%6,%7}, {%8,%9}, {%0,%1,%2,%3};\n"
                 : "+f"(c[0]), "+f"(c[1]), "+f"(c[2]), "+f"(c[3])
                 : "r"(a[0]), "r"(a[1]), "r"(a[2]), "r"(a[3]), "r"(b[0]), "r"(b[1]));
}

// ---------------- tensor-core GEMM (proven in R5) --------------------------
#define GK_CHUNK 32
#define GPAD 40
#define G_ARR_BYTES (128 * GPAD * 2)
#define G_STAGE_BYTES (4 * G_ARR_BYTES)
#define G_SMEM_BYTES (2 * G_STAGE_BYTES)

__device__ __forceinline__ void mma_gemm_body(
    const __nv_bfloat16* __restrict__ Ah, const __nv_bfloat16* __restrict__ Al,
    const __nv_bfloat16* __restrict__ Bh, const __nv_bfloat16* __restrict__ Bl,
    float* __restrict__ C, const float* __restrict__ bias)
{
    extern __shared__ char smem_raw[];
    const int tid = threadIdx.x;
    const int lane = tid & 31;
    const int wid = tid >> 5;
    const int bM = blockIdx.y * 128;
    const int bN = blockIdx.x * 128;
    const int wM = (wid >> 2) * 64;
    const int wN = (wid & 3) * 32;

    const uint32_t smem_base = (uint32_t)__cvta_generic_to_shared(smem_raw);

    const int ldr = tid >> 2;
    const int ldc = (tid & 3) * 8;

    const __nv_bfloat16* pAh = Ah + (size_t)(bM + ldr) * DD + ldc;
    const __nv_bfloat16* pAl = Al + (size_t)(bM + ldr) * DD + ldc;
    const __nv_bfloat16* pBh = Bh + (size_t)(bN + ldr) * DD + ldc;
    const __nv_bfloat16* pBl = Bl + (size_t)(bN + ldr) * DD + ldc;

    const uint32_t dbase = smem_base + ldr * (GPAD * 2) + ldc * 2;
    const uint32_t rowhalf = 64 * GPAD * 2;

    float acc[4][4][4];
#pragma unroll
    for (int mi = 0; mi < 4; mi++)
#pragma unroll
        for (int ni = 0; ni < 4; ni++)
#pragma unroll
            for (int r = 0; r < 4; r++) acc[mi][ni][r] = 0.f;

    auto issue = [&](int buf, int k0) {
        uint32_t d = dbase + buf * G_STAGE_BYTES;
        cp16(d,                              pAh + k0);
        cp16(d + rowhalf,                    pAh + 64 * DD + k0);
        cp16(d + G_ARR_BYTES,                pAl + k0);
        cp16(d + G_ARR_BYTES + rowhalf,      pAl + 64 * DD + k0);
        cp16(d + 2 * G_ARR_BYTES,            pBh + k0);
        cp16(d + 2 * G_ARR_BYTES + rowhalf,  pBh + 64 * DD + k0);
        cp16(d + 3 * G_ARR_BYTES,            pBl + k0);
        cp16(d + 3 * G_ARR_BYTES + rowhalf,  pBl + 64 * DD + k0);
        asm volatile("cp.async.commit_group;\n");
    };

    issue(0, 0);
    const int NCH = DD / GK_CHUNK;
    for (int c = 0; c < NCH; c++) {
        if (c + 1 < NCH) {
            issue((c + 1) & 1, (c + 1) * GK_CHUNK);
            asm volatile("cp.async.wait_group 1;\n");
        } else {
            asm volatile("cp.async.wait_group 0;\n");
        }
        __syncthreads();

        uint32_t sb = smem_base + (c & 1) * G_STAGE_BYTES;
#pragma unroll
        for (int kh = 0; kh < 2; kh++) {
            uint32_t ah[4][4], al[4][4];
            const int arow = wM + (lane & 15);
            const int acol = kh * 16 + ((lane >> 4) << 3);
#pragma unroll
            for (int mi = 0; mi < 4; mi++) {
                uint32_t addr = sb + (uint32_t)((arow + mi * 16) * (GPAD * 2) + acol * 2);
                ldsm_x4(ah[mi], addr);
                ldsm_x4(al[mi], addr + G_ARR_BYTES);
            }
            const int brow = wN + (lane & 7);
            const int bcol = kh * 16 + ((lane >> 3) & 1) * 8;
#pragma unroll
            for (int ni = 0; ni < 4; ni++) {
                uint32_t baddr = sb + 2 * G_ARR_BYTES +
                                 (uint32_t)((brow + ni * 8) * (GPAD * 2) + bcol * 2);
                uint32_t bh[2], bl[2];
                ldsm_x2(bh, baddr);
                ldsm_x2(bl, baddr + G_ARR_BYTES);
#pragma unroll
                for (int mi = 0; mi < 4; mi++) {
                    mma16816(acc[mi][ni], ah[mi], bh);
                    mma16816(acc[mi][ni], ah[mi], bl);
                    mma16816(acc[mi][ni], al[mi], bh);
                }
            }
        }
        __syncthreads();
    }

#pragma unroll
    for (int mi = 0; mi < 4; mi++) {
        int m0 = bM + wM + mi * 16 + (lane >> 2);
#pragma unroll
        for (int ni = 0; ni < 4; ni++) {
            int n = bN + wN + ni * 8 + (lane & 3) * 2;
            float b0 = 0.f, b1 = 0.f;
            if (bias) { b0 = bias[n]; b1 = bias[n + 1]; }
            float2 r0; r0.x = acc[mi][ni][0] + b0; r0.y = acc[mi][ni][1] + b1;
            float2 r1; r1.x = acc[mi][ni][2] + b0; r1.y = acc[mi][ni][3] + b1;
            *(float2*)&C[(size_t)m0 * DD + n]       = r0;
            *(float2*)&C[(size_t)(m0 + 8) * DD + n] = r1;
        }
    }
}

__global__ void __launch_bounds__(256) qkv_mma_kernel() {
    int z = blockIdx.z;
    float* C = (z == 0) ? g_q : (z == 1) ? g_k : g_v;
    mma_gemm_body(g_xh, g_xl, g_wh[z], g_wl[z], C, nullptr);
}

__global__ void __launch_bounds__(256) out_mma_kernel(const float* __restrict__ bo,
                                                      float* __restrict__ out) {
    mma_gemm_body(g_ah, g_al, g_wh[3], g_wl[3], out, bo);
}

// ---------------- RoPE apply (q and k, in place) ---------------------------
__global__ void rope_apply_kernel() {
    int idx = blockIdx.x * blockDim.x + threadIdx.x;
    if (idx >= BT * HH * 32) return;
    int bt = idx >> 9;
    int r = idx & 511;
    int h = r >> 5;
    int i = r & 31;
    int t = bt & (TT - 1);
    float c = g_cos[t * 32 + i];
    float s = g_sin[t * 32 + i];
    int base = bt * DD + h * DH + i;
    float q0 = g_q[base], q1 = g_q[base + 32];
    g_q[base]      = q0 * c - q1 * s;
    g_q[base + 32] = q1 * c + q0 * s;
    float k0 = g_k[base], k1 = g_k[base + 32];
    g_k[base]      = k0 * c - k1 * s;
    g_k[base + 32] = k1 * c + k0 * s;
}

// ---------------- tensor-core sliding-window attention ---------------------
// CTA = (q-tile 64, head, batch). Keys window padded to 192 (tail zeroed).
// Phase 1: scores via mma (hi/lo split), warps = 4 q-tiles x 2 key-halves.
// Split softmax across key-half warps via smem max/sum exchange.
// Phase 2: PV via mma; P (bf16 hi/lo) from smem, V transposed in smem.
// Output written directly as bf16 hi/lo into g_ah/g_al.

#define QT 64
#define KTM 192
#define QK_PITCH 72      // bf16 elements per row for Q/K tiles (64+8)
#define PV_PITCH 200     // bf16 elements per row for P/Vt tiles (192+8)

#define AOFF_QH 0
#define AOFF_QL (AOFF_QH + 64*QK_PITCH*2)
#define AOFF_KH (AOFF_QL + 64*QK_PITCH*2)
#define AOFF_KL (AOFF_KH + 192*QK_PITCH*2)
#define AOFF_VH (AOFF_KL + 192*QK_PITCH*2)
#define AOFF_VL (AOFF_VH + 64*PV_PITCH*2)
#define AOFF_PH (AOFF_VL + 64*PV_PITCH*2)
#define AOFF_PL (AOFF_PH + 64*PV_PITCH*2)
#define AOFF_MAX (AOFF_PL + 64*PV_PITCH*2)
#define AOFF_SUM (AOFF_MAX + 64*2*4)
#define ATT_SMEM_BYTES (AOFF_SUM + 64*2*4)

__global__ void __launch_bounds__(256) attn_kernel() {
    extern __shared__ char sm[];
    const uint32_t smem_u32 = (uint32_t)__cvta_generic_to_shared(sm);

    const int b = blockIdx.z, h = blockIdx.y;
    const int q0 = blockIdx.x * QT;
    const int tid = threadIdx.x;
    const int lane = tid & 31;
    const int wid = tid >> 5;
    const int kmin = max(0, q0 - (WIN - 1));
    const int numK = q0 + QT - kmin;      // <= 191
    const int hoff = h * DH;

    const float* kbase = g_k + (size_t)(b * TT + kmin) * DD + hoff;
    const float* vbase = g_v + (size_t)(b * TT + kmin) * DD + hoff;
    const float* qbase = g_q + (size_t)(b * TT + q0) * DD + hoff;

    __nv_bfloat16* sQh = (__nv_bfloat16*)(sm + AOFF_QH);
    __nv_bfloat16* sQl = (__nv_bfloat16*)(sm + AOFF_QL);
    __nv_bfloat16* sKh = (__nv_bfloat16*)(sm + AOFF_KH);
    __nv_bfloat16* sKl = (__nv_bfloat16*)(sm + AOFF_KL);
    __nv_bfloat16* sVh = (__nv_bfloat16*)(sm + AOFF_VH);
    __nv_bfloat16* sVl = (__nv_bfloat16*)(sm + AOFF_VL);
    __nv_bfloat16* sPh = (__nv_bfloat16*)(sm + AOFF_PH);
    __nv_bfloat16* sPl = (__nv_bfloat16*)(sm + AOFF_PL);
    float* sMax = (float*)(sm + AOFF_MAX);
    float* sSum = (float*)(sm + AOFF_SUM);

    // ---- load K (rows), V (transposed), Q; fp32 -> bf16 hi/lo ----
    for (int e = tid; e < KTM * 16; e += 256) {
        int jl = e >> 4;
        int dq = (e & 15) * 4;
        float4 kv = make_float4(0.f, 0.f, 0.f, 0.f);
        float4 vv = make_float4(0.f, 0.f, 0.f, 0.f);
        if (jl < numK) {
            kv = *(const float4*)(kbase + (size_t)jl * DD + dq);
            vv = *(const float4*)(vbase + (size_t)jl * DD + dq);
        }
        __nv_bfloat16 kh0,kh1,kh2,kh3,kl0,kl1,kl2,kl3;
        split2(kv.x,kh0,kl0); split2(kv.y,kh1,kl1);
        split2(kv.z,kh2,kl2); split2(kv.w,kh3,kl3);
        int kb = jl * QK_PITCH + dq;
        *(__nv_bfloat162*)&sKh[kb]     = __nv_bfloat162{kh0,kh1};
        *(__nv_bfloat162*)&sKh[kb + 2] = __nv_bfloat162{kh2,kh3};
        *(__nv_bfloat162*)&sKl[kb]     = __nv_bfloat162{kl0,kl1};
        *(__nv_bfloat162*)&sKl[kb + 2] = __nv_bfloat162{kl2,kl3};
        __nv_bfloat16 vh[4], vl[4];
        split2(vv.x,vh[0],vl[0]); split2(vv.y,vh[1],vl[1]);
        split2(vv.z,vh[2],vl[2]); split2(vv.w,vh[3],vl[3]);
#pragma unroll
        for (int i = 0; i < 4; i++) {
            sVh[(dq + i) * PV_PITCH + jl] = vh[i];
            sVl[(dq + i) * PV_PITCH + jl] = vl[i];
        }
    }
    for (int e = tid; e < QT * 16; e += 256) {
        int qi = e >> 4;
        int dq = (e & 15) * 4;
        float4 qv = *(const float4*)(qbase + (size_t)qi * DD + dq);
        __nv_bfloat16 h0,h1,h2,h3,l0,l1,l2,l3;
        split2(qv.x,h0,l0); split2(qv.y,h1,l1);
        split2(qv.z,h2,l2); split2(qv.w,h3,l3);
        int qb = qi * QK_PITCH + dq;
        *(__nv_bfloat162*)&sQh[qb]     = __nv_bfloat162{h0,h1};
        *(__nv_bfloat162*)&sQh[qb + 2] = __nv_bfloat162{h2,h3};
        *(__nv_bfloat162*)&sQl[qb]     = __nv_bfloat162{l0,l1};
        *(__nv_bfloat162*)&sQl[qb + 2] = __nv_bfloat162{l2,l3};
    }
    __syncthreads();

    // ---- phase 1: scores = Q @ K^T (hi/lo mma) ----
    const int mi = wid & 3;       // q tile (16 rows)
    const int khf = wid >> 2;     // key half (96 keys)
    const int g = lane >> 2;
    const int t2 = (lane & 3) * 2;

    float acc[12][4];
#pragma unroll
    for (int nt = 0; nt < 12; nt++)
#pragma unroll
        for (int r = 0; r < 4; r++) acc[nt][r] = 0.f;

#pragma unroll
    for (int ks = 0; ks < 4; ks++) {
        uint32_t ah[4], al[4];
        int arow = mi * 16 + (lane & 15);
        int acol = ks * 16 + ((lane >> 4) << 3);
        uint32_t aaddr = smem_u32 + AOFF_QH + (uint32_t)(arow * QK_PITCH + acol) * 2;
        ldsm_x4(ah, aaddr);
        ldsm_x4(al, aaddr + (AOFF_QL - AOFF_QH));
#pragma unroll
        for (int nt = 0; nt < 12; nt++) {
            int brow = khf * 96 + nt * 8 + (lane & 7);
            int bcol = ks * 16 + ((lane >> 3) & 1) * 8;
            uint32_t baddr = smem_u32 + AOFF_KH + (uint32_t)(brow * QK_PITCH + bcol) * 2;
            uint32_t bh[2], bl[2];
            ldsm_x2(bh, baddr);
            ldsm_x2(bl, baddr + (AOFF_KL - AOFF_KH));
            mma16816(acc[nt], ah, bh);
            mma16816(acc[nt], ah, bl);
            mma16816(acc[nt], al, bh);
        }
    }

    // ---- mask + partial softmax (per key-half) ----
    const float sm_scale = 0.125f;
    float pmax[2], psum[2];
#pragma unroll
    for (int rp = 0; rp < 2; rp++) {
        int qrow = mi * 16 + g + rp * 8;
        int qg = q0 + qrow;
        int lo = max(0, qg - (WIN - 1)) - kmin;
        int hi = qg - kmin;
        float mx = -1e30f;
#pragma unroll
        for (int nt = 0; nt < 12; nt++) {
#pragma unroll
            for (int c = 0; c < 2; c++) {
                int kl = khf * 96 + nt * 8 + t2 + c;
                float v = acc[nt][rp * 2 + c] * sm_scale;
                v = (kl >= lo && kl <= hi) ? v : -1e30f;
                acc[nt][rp * 2 + c] = v;
                mx = fmaxf(mx, v);
            }
        }
        mx = fmaxf(mx, __shfl_xor_sync(0xffffffffu, mx, 1));
        mx = fmaxf(mx, __shfl_xor_sync(0xffffffffu, mx, 2));
        float sum = 0.f;
#pragma unroll
        for (int nt = 0; nt < 12; nt++) {
#pragma unroll
            for (int c = 0; c < 2; c++) {
                float e = __expf(acc[nt][rp * 2 + c] - mx);
                acc[nt][rp * 2 + c] = e;
                sum += e;
            }
        }
        sum += __shfl_xor_sync(0xffffffffu, sum, 1);
        sum += __shfl_xor_sync(0xffffffffu, sum, 2);
        pmax[rp] = mx;
        psum[rp] = sum;
        if ((lane & 3) == 0) {
            sMax[qrow * 2 + khf] = mx;
            sSum[qrow * 2 + khf] = sum;
        }
    }
    __syncthreads();

    // ---- combine halves, write P (bf16 hi/lo) to smem ----
#pragma unroll
    for (int rp = 0; rp < 2; rp++) {
        int qrow = mi * 16 + g + rp * 8;
        float m0 = sMax[qrow * 2 + 0], m1 = sMax[qrow * 2 + 1];
        float s0 = sSum[qrow * 2 + 0], s1 = sSum[qrow * 2 + 1];
        float M = fmaxf(m0, m1);
        float S = s0 * __expf(m0 - M) + s1 * __expf(m1 - M);
        float factor = __expf(pmax[rp] - M) / S;
#pragma unroll
        for (int nt = 0; nt < 12; nt++) {
            float p0 = acc[nt][rp * 2 + 0] * factor;
            float p1 = acc[nt][rp * 2 + 1] * factor;
            __nv_bfloat16 h0,h1,l0,l1;
            split2(p0,h0,l0); split2(p1,h1,l1);
            int idx = qrow * PV_PITCH + khf * 96 + nt * 8 + t2;
            *(__nv_bfloat162*)&sPh[idx] = __nv_bfloat162{h0,h1};
            *(__nv_bfloat162*)&sPl[idx] = __nv_bfloat162{l0,l1};
        }
    }
    __syncthreads();

    // ---- phase 2: out = P @ V (hi/lo mma) ----
    const int nh = wid >> 2;      // dim half (32 dims)
    float oacc[4][4];
#pragma unroll
    for (int nt = 0; nt < 4; nt++)
#pragma unroll
        for (int r = 0; r < 4; r++) oacc[nt][r] = 0.f;

#pragma unroll
    for (int ks = 0; ks < 12; ks++) {
        uint32_t ah[4], al[4];
        int arow = mi * 16 + (lane & 15);
        int acol = ks * 16 + ((lane >> 4) << 3);
        uint32_t aaddr = smem_u32 + AOFF_PH + (uint32_t)(arow * PV_PITCH + acol) * 2;
        ldsm_x4(ah, aaddr);
        ldsm_x4(al, aaddr + (AOFF_PL - AOFF_PH));
#pragma unroll
        for (int nt = 0; nt < 4; nt++) {
            int brow = nh * 32 + nt * 8 + (lane & 7);
            int bcol = ks * 16 + ((lane >> 3) & 1) * 8;
            uint32_t baddr = smem_u32 + AOFF_VH + (uint32_t)(brow * PV_PITCH + bcol) * 2;
            uint32_t bh[2], bl[2];
            ldsm_x2(bh, baddr);
            ldsm_x2(bl, baddr + (AOFF_VL - AOFF_VH));
            mma16816(oacc[nt], ah, bh);
            mma16816(oacc[nt], ah, bl);
            mma16816(oacc[nt], al, bh);
        }
    }

    // ---- epilogue: split to bf16 hi/lo, write g_ah/g_al ----
#pragma unroll
    for (int nt = 0; nt < 4; nt++) {
        int col = hoff + nh * 32 + nt * 8 + t2;
        size_t r0 = (size_t)(b * TT + q0 + mi * 16 + g) * DD + col;
        size_t r1 = r0 + (size_t)8 * DD;
        __nv_bfloat16 h0,h1,l0,l1;
        split2(oacc[nt][0],h0,l0); split2(oacc[nt][1],h1,l1);
        *(__nv_bfloat162*)&g_ah[r0] = __nv_bfloat162{h0,h1};
        *(__nv_bfloat162*)&g_al[r0] = __nv_bfloat162{l0,l1};
        split2(oacc[nt][2],h0,l0); split2(oacc[nt][3],h1,l1);
        *(__nv_bfloat162*)&g_ah[r1] = __nv_bfloat162{h0,h1};
        *(__nv_bfloat162*)&g_al[r1] = __nv_bfloat162{l0,l1};
    }
}

// ---------------- launch ----------------------------------------------------
extern "C" void kernel_launch(void* const* d_in, const int* in_sizes, int n_in,
                              void* d_out, int out_size) {
    const float* x  = (const float*)d_in[0];
    const float* Wq = (const float*)d_in[1];
    const float* Wk = (const float*)d_in[2];
    const float* Wv = (const float*)d_in[3];
    const float* Wo = (const float*)d_in[4];
    const float* bo = (const float*)d_in[5];
    float* out = (float*)d_out;

    cudaFuncSetAttribute(attn_kernel, cudaFuncAttributeMaxDynamicSharedMemorySize,
                         ATT_SMEM_BYTES);
    cudaFuncSetAttribute(qkv_mma_kernel, cudaFuncAttributeMaxDynamicSharedMemorySize,
                         G_SMEM_BYTES);
    cudaFuncSetAttribute(out_mma_kernel, cudaFuncAttributeMaxDynamicSharedMemorySize,
                         G_SMEM_BYTES);

    rope_table_kernel<<<(TT * 32 + 255) / 256, 256>>>();

    cvt_x_kernel<<<(BT * DD / 4 + 255) / 256, 256>>>(x);
    cvt_w_kernel<<<(DD * DD / 4 + 255) / 256, 256>>>(Wq, 0);
    cvt_w_kernel<<<(DD * DD / 4 + 255) / 256, 256>>>(Wk, 1);
    cvt_w_kernel<<<(DD * DD / 4 + 255) / 256, 256>>>(Wv, 2);
    cvt_w_kernel<<<(DD * DD / 4 + 255) / 256, 256>>>(Wo, 3);

    dim3 gqkv(DD / 128, BT / 128, 3);
    qkv_mma_kernel<<<gqkv, 256, G_SMEM_BYTES>>>();

    rope_apply_kernel<<<(BT * HH * 32 + 255) / 256, 256>>>();

    attn_kernel<<<dim3(TT / QT, HH, BB), 256, ATT_SMEM_BYTES>>>();

    dim3 go(DD / 128, BT / 128, 1);
    out_mma_kernel<<<go, 256, G_SMEM_BYTES>>>(bo, out);
}

// round 7
// speedup vs baseline: 4.8328x; 1.0658x over previous
#include <cuda_runtime.h>
#include <cuda_bf16.h>
#include <math.h>
#include <stdint.h>

// Problem constants
#define BB 2
#define TT 2048
#define DD 1024
#define HH 16
#define DH 64
#define WIN 128
#define BT (BB*TT)          // 4096

// ---------------- scratch (device globals) ----------------------------------
__device__ float g_cos[TT * 32];
__device__ float g_sin[TT * 32];

// bf16 hi/lo operands
__device__ __nv_bfloat16 g_xh[BT * DD];
__device__ __nv_bfloat16 g_xl[BT * DD];
__device__ __nv_bfloat16 g_wh[4][DD * DD];
__device__ __nv_bfloat16 g_wl[4][DD * DD];
__device__ __nv_bfloat16 g_qh[BT * DD];
__device__ __nv_bfloat16 g_ql[BT * DD];
__device__ __nv_bfloat16 g_kh[BT * DD];
__device__ __nv_bfloat16 g_kl[BT * DD];
__device__ __nv_bfloat16 g_vh[BT * DD];
__device__ __nv_bfloat16 g_vl[BT * DD];
__device__ __nv_bfloat16 g_ah[BT * DD];   // attention output hi
__device__ __nv_bfloat16 g_al[BT * DD];   // attention output lo

// ---------------- RoPE tables ----------------------------------------------
__global__ void rope_table_kernel() {
    int idx = blockIdx.x * blockDim.x + threadIdx.x;
    if (idx >= TT * 32) return;
    int t = idx >> 5;
    int i = idx & 31;
    double inv = exp(-log(10000.0) * (double)(2 * i) / 64.0);
    double a = (double)t * inv;
    g_cos[idx] = (float)cos(a);
    g_sin[idx] = (float)sin(a);
}

// ---------------- fp32 -> bf16 hi/lo split ----------------------------------
__device__ __forceinline__ void split2(float x, __nv_bfloat16& h, __nv_bfloat16& l) {
    h = __float2bfloat16(x);
    l = __float2bfloat16(x - __bfloat162float(h));
}

__global__ void cvt_x_kernel(const float* __restrict__ src) {
    int i = blockIdx.x * blockDim.x + threadIdx.x;
    if (i >= BT * DD / 4) return;
    float4 v = ((const float4*)src)[i];
    __nv_bfloat16 h0,h1,h2,h3,l0,l1,l2,l3;
    split2(v.x,h0,l0); split2(v.y,h1,l1); split2(v.z,h2,l2); split2(v.w,h3,l3);
    ((__nv_bfloat162*)g_xh)[i*2+0] = __nv_bfloat162{h0,h1};
    ((__nv_bfloat162*)g_xh)[i*2+1] = __nv_bfloat162{h2,h3};
    ((__nv_bfloat162*)g_xl)[i*2+0] = __nv_bfloat162{l0,l1};
    ((__nv_bfloat162*)g_xl)[i*2+1] = __nv_bfloat162{l2,l3};
}

__global__ void cvt_w_all_kernel(const float* __restrict__ Wq, const float* __restrict__ Wk,
                                 const float* __restrict__ Wv, const float* __restrict__ Wo) {
    int z = blockIdx.y;
    const float* src = (z == 0) ? Wq : (z == 1) ? Wk : (z == 2) ? Wv : Wo;
    int i = blockIdx.x * blockDim.x + threadIdx.x;
    if (i >= DD * DD / 4) return;
    float4 v = ((const float4*)src)[i];
    __nv_bfloat16 h0,h1,h2,h3,l0,l1,l2,l3;
    split2(v.x,h0,l0); split2(v.y,h1,l1); split2(v.z,h2,l2); split2(v.w,h3,l3);
    ((__nv_bfloat162*)g_wh[z])[i*2+0] = __nv_bfloat162{h0,h1};
    ((__nv_bfloat162*)g_wh[z])[i*2+1] = __nv_bfloat162{h2,h3};
    ((__nv_bfloat162*)g_wl[z])[i*2+0] = __nv_bfloat162{l0,l1};
    ((__nv_bfloat162*)g_wl[z])[i*2+1] = __nv_bfloat162{l2,l3};
}

// ---------------- mma helpers -----------------------------------------------
__device__ __forceinline__ void cp16(uint32_t dst, const void* src) {
    asm volatile("cp.async.cg.shared.global [%0], [%1], 16;\n" :: "r"(dst), "l"(src));
}
__device__ __forceinline__ void cp16z(uint32_t dst, const void* src, int sz) {
    asm volatile("cp.async.cg.shared.global [%0], [%1], 16, %2;\n"
                 :: "r"(dst), "l"(src), "r"(sz));
}
__device__ __forceinline__ void ldsm_x4(uint32_t* r, uint32_t a) {
    asm volatile("ldmatrix.sync.aligned.m8n8.x4.shared.b16 {%0,%1,%2,%3}, [%4];\n"
                 : "=r"(r[0]), "=r"(r[1]), "=r"(r[2]), "=r"(r[3]) : "r"(a));
}
__device__ __forceinline__ void ldsm_x2(uint32_t* r, uint32_t a) {
    asm volatile("ldmatrix.sync.aligned.m8n8.x2.shared.b16 {%0,%1}, [%2];\n"
                 : "=r"(r[0]), "=r"(r[1]) : "r"(a));
}
__device__ __forceinline__ void ldsm_x2t(uint32_t* r, uint32_t a) {
    asm volatile("ldmatrix.sync.aligned.m8n8.x2.trans.shared.b16 {%0,%1}, [%2];\n"
                 : "=r"(r[0]), "=r"(r[1]) : "r"(a));
}
__device__ __forceinline__ void mma16816(float* c, const uint32_t* a, const uint32_t* b) {
    asm volatile("mma.sync.aligned.m16n8k16.row.col.f32.bf16.bf16.f32 "
                 "{%0,%1,%2,%3}, {%4,%5,%6,%7}, {%8,%9}, {%0,%1,%2,%3};\n"
                 : "+f"(c[0]), "+f"(c[1]), "+f"(c[2]), "+f"(c[3])
                 : "r"(a[0]), "r"(a[1]), "r"(a[2]), "r"(a[3]), "r"(b[0]), "r"(b[1]));
}

// ---------------- tensor-core GEMM (hi/lo split) ----------------------------
#define GK_CHUNK 32
#define GPAD 40
#define G_ARR_BYTES (128 * GPAD * 2)
#define G_STAGE_BYTES (4 * G_ARR_BYTES)
#define G_SMEM_BYTES (2 * G_STAGE_BYTES)

// If Ch != nullptr: write bf16 hi/lo split to Ch/Cl. Else fp32 to C (+bias).
__device__ __forceinline__ void mma_gemm_body(
    const __nv_bfloat16* __restrict__ Ah, const __nv_bfloat16* __restrict__ Al,
    const __nv_bfloat16* __restrict__ Bh, const __nv_bfloat16* __restrict__ Bl,
    float* __restrict__ C, const float* __restrict__ bias,
    __nv_bfloat16* __restrict__ Ch, __nv_bfloat16* __restrict__ Cl)
{
    extern __shared__ char smem_raw[];
    const int tid = threadIdx.x;
    const int lane = tid & 31;
    const int wid = tid >> 5;
    const int bM = blockIdx.y * 128;
    const int bN = blockIdx.x * 128;
    const int wM = (wid >> 2) * 64;
    const int wN = (wid & 3) * 32;

    const uint32_t smem_base = (uint32_t)__cvta_generic_to_shared(smem_raw);

    const int ldr = tid >> 2;
    const int ldc = (tid & 3) * 8;

    const __nv_bfloat16* pAh = Ah + (size_t)(bM + ldr) * DD + ldc;
    const __nv_bfloat16* pAl = Al + (size_t)(bM + ldr) * DD + ldc;
    const __nv_bfloat16* pBh = Bh + (size_t)(bN + ldr) * DD + ldc;
    const __nv_bfloat16* pBl = Bl + (size_t)(bN + ldr) * DD + ldc;

    const uint32_t dbase = smem_base + ldr * (GPAD * 2) + ldc * 2;
    const uint32_t rowhalf = 64 * GPAD * 2;

    float acc[4][4][4];
#pragma unroll
    for (int mi = 0; mi < 4; mi++)
#pragma unroll
        for (int ni = 0; ni < 4; ni++)
#pragma unroll
            for (int r = 0; r < 4; r++) acc[mi][ni][r] = 0.f;

    auto issue = [&](int buf, int k0) {
        uint32_t d = dbase + buf * G_STAGE_BYTES;
        cp16(d,                              pAh + k0);
        cp16(d + rowhalf,                    pAh + 64 * DD + k0);
        cp16(d + G_ARR_BYTES,                pAl + k0);
        cp16(d + G_ARR_BYTES + rowhalf,      pAl + 64 * DD + k0);
        cp16(d + 2 * G_ARR_BYTES,            pBh + k0);
        cp16(d + 2 * G_ARR_BYTES + rowhalf,  pBh + 64 * DD + k0);
        cp16(d + 3 * G_ARR_BYTES,            pBl + k0);
        cp16(d + 3 * G_ARR_BYTES + rowhalf,  pBl + 64 * DD + k0);
        asm volatile("cp.async.commit_group;\n");
    };

    issue(0, 0);
    const int NCH = DD / GK_CHUNK;
    for (int c = 0; c < NCH; c++) {
        if (c + 1 < NCH) {
            issue((c + 1) & 1, (c + 1) * GK_CHUNK);
            asm volatile("cp.async.wait_group 1;\n");
        } else {
            asm volatile("cp.async.wait_group 0;\n");
        }
        __syncthreads();

        uint32_t sb = smem_base + (c & 1) * G_STAGE_BYTES;
#pragma unroll
        for (int kh = 0; kh < 2; kh++) {
            uint32_t ah[4][4], al[4][4];
            const int arow = wM + (lane & 15);
            const int acol = kh * 16 + ((lane >> 4) << 3);
#pragma unroll
            for (int mi = 0; mi < 4; mi++) {
                uint32_t addr = sb + (uint32_t)((arow + mi * 16) * (GPAD * 2) + acol * 2);
                ldsm_x4(ah[mi], addr);
                ldsm_x4(al[mi], addr + G_ARR_BYTES);
            }
            const int brow = wN + (lane & 7);
            const int bcol = kh * 16 + ((lane >> 3) & 1) * 8;
#pragma unroll
            for (int ni = 0; ni < 4; ni++) {
                uint32_t baddr = sb + 2 * G_ARR_BYTES +
                                 (uint32_t)((brow + ni * 8) * (GPAD * 2) + bcol * 2);
                uint32_t bh[2], bl[2];
                ldsm_x2(bh, baddr);
                ldsm_x2(bl, baddr + G_ARR_BYTES);
#pragma unroll
                for (int mi = 0; mi < 4; mi++) {
                    mma16816(acc[mi][ni], ah[mi], bh);
                    mma16816(acc[mi][ni], ah[mi], bl);
                    mma16816(acc[mi][ni], al[mi], bh);
                }
            }
        }
        __syncthreads();
    }

#pragma unroll
    for (int mi = 0; mi < 4; mi++) {
        int m0 = bM + wM + mi * 16 + (lane >> 2);
#pragma unroll
        for (int ni = 0; ni < 4; ni++) {
            int n = bN + wN + ni * 8 + (lane & 3) * 2;
            if (Ch) {
                __nv_bfloat16 h0,h1,l0,l1;
                split2(acc[mi][ni][0],h0,l0); split2(acc[mi][ni][1],h1,l1);
                *(__nv_bfloat162*)&Ch[(size_t)m0 * DD + n] = __nv_bfloat162{h0,h1};
                *(__nv_bfloat162*)&Cl[(size_t)m0 * DD + n] = __nv_bfloat162{l0,l1};
                split2(acc[mi][ni][2],h0,l0); split2(acc[mi][ni][3],h1,l1);
                *(__nv_bfloat162*)&Ch[(size_t)(m0 + 8) * DD + n] = __nv_bfloat162{h0,h1};
                *(__nv_bfloat162*)&Cl[(size_t)(m0 + 8) * DD + n] = __nv_bfloat162{l0,l1};
            } else {
                float b0 = 0.f, b1 = 0.f;
                if (bias) { b0 = bias[n]; b1 = bias[n + 1]; }
                float2 r0; r0.x = acc[mi][ni][0] + b0; r0.y = acc[mi][ni][1] + b1;
                float2 r1; r1.x = acc[mi][ni][2] + b0; r1.y = acc[mi][ni][3] + b1;
                *(float2*)&C[(size_t)m0 * DD + n]       = r0;
                *(float2*)&C[(size_t)(m0 + 8) * DD + n] = r1;
            }
        }
    }
}

__global__ void __launch_bounds__(256) qkv_mma_kernel() {
    int z = blockIdx.z;
    __nv_bfloat16* Ch = (z == 0) ? g_qh : (z == 1) ? g_kh : g_vh;
    __nv_bfloat16* Cl = (z == 0) ? g_ql : (z == 1) ? g_kl : g_vl;
    mma_gemm_body(g_xh, g_xl, g_wh[z], g_wl[z], nullptr, nullptr, Ch, Cl);
}

__global__ void __launch_bounds__(256) out_mma_kernel(const float* __restrict__ bo,
                                                      float* __restrict__ out) {
    mma_gemm_body(g_ah, g_al, g_wh[3], g_wl[3], out, bo, nullptr, nullptr);
}

// ---------------- RoPE apply on hi/lo arrays (q and k, in place) ------------
__global__ void rope_apply_kernel() {
    int idx = blockIdx.x * blockDim.x + threadIdx.x;
    if (idx >= BT * HH * 32) return;
    int bt = idx >> 9;
    int r = idx & 511;
    int h = r >> 5;
    int i = r & 31;
    int t = bt & (TT - 1);
    float c = g_cos[t * 32 + i];
    float s = g_sin[t * 32 + i];
    int base = bt * DD + h * DH + i;

    float q0 = __bfloat162float(g_qh[base]) + __bfloat162float(g_ql[base]);
    float q1 = __bfloat162float(g_qh[base + 32]) + __bfloat162float(g_ql[base + 32]);
    float r0 = q0 * c - q1 * s;
    float r1 = q1 * c + q0 * s;
    __nv_bfloat16 hh, ll;
    split2(r0, hh, ll); g_qh[base] = hh;      g_ql[base] = ll;
    split2(r1, hh, ll); g_qh[base + 32] = hh; g_ql[base + 32] = ll;

    float k0 = __bfloat162float(g_kh[base]) + __bfloat162float(g_kl[base]);
    float k1 = __bfloat162float(g_kh[base + 32]) + __bfloat162float(g_kl[base + 32]);
    r0 = k0 * c - k1 * s;
    r1 = k1 * c + k0 * s;
    split2(r0, hh, ll); g_kh[base] = hh;      g_kl[base] = ll;
    split2(r1, hh, ll); g_kh[base + 32] = hh; g_kl[base + 32] = ll;
}

// ---------------- tensor-core sliding-window attention ----------------------
// All operands already bf16 hi/lo in gmem -> pure cp.async loads.
// V kept row-major; phase-2 B fragments via ldmatrix.trans.

#define QT 64
#define KTM 192
#define QK_PITCH 72      // bf16/row (144B: 16B-aligned, bank-conflict-free)
#define PV_PITCH 200     // bf16/row for P (400B)

#define AOFF_QH 0
#define AOFF_QL (AOFF_QH + 64*QK_PITCH*2)
#define AOFF_KH (AOFF_QL + 64*QK_PITCH*2)
#define AOFF_KL (AOFF_KH + 192*QK_PITCH*2)
#define AOFF_VH (AOFF_KL + 192*QK_PITCH*2)
#define AOFF_VL (AOFF_VH + 192*QK_PITCH*2)
#define AOFF_PH (AOFF_VL + 192*QK_PITCH*2)
#define AOFF_PL (AOFF_PH + 64*PV_PITCH*2)
#define AOFF_MAX (AOFF_PL + 64*PV_PITCH*2)
#define AOFF_SUM (AOFF_MAX + 64*2*4)
#define ATT_SMEM_BYTES (AOFF_SUM + 64*2*4)

__global__ void __launch_bounds__(256) attn_kernel() {
    extern __shared__ char sm[];
    const uint32_t smem_u32 = (uint32_t)__cvta_generic_to_shared(sm);

    const int b = blockIdx.z, h = blockIdx.y;
    const int q0 = blockIdx.x * QT;
    const int tid = threadIdx.x;
    const int lane = tid & 31;
    const int wid = tid >> 5;
    const int kmin = max(0, q0 - (WIN - 1));
    const int numK = q0 + QT - kmin;      // <= 191
    const int hoff = h * DH;

    const __nv_bfloat16* khb = g_kh + (size_t)(b * TT + kmin) * DD + hoff;
    const __nv_bfloat16* klb = g_kl + (size_t)(b * TT + kmin) * DD + hoff;
    const __nv_bfloat16* vhb = g_vh + (size_t)(b * TT + kmin) * DD + hoff;
    const __nv_bfloat16* vlb = g_vl + (size_t)(b * TT + kmin) * DD + hoff;
    const __nv_bfloat16* qhb = g_qh + (size_t)(b * TT + q0) * DD + hoff;
    const __nv_bfloat16* qlb = g_ql + (size_t)(b * TT + q0) * DD + hoff;

    __nv_bfloat16* sPh = (__nv_bfloat16*)(sm + AOFF_PH);
    __nv_bfloat16* sPl = (__nv_bfloat16*)(sm + AOFF_PL);
    float* sMax = (float*)(sm + AOFF_MAX);
    float* sSum = (float*)(sm + AOFF_SUM);

    // ---- async loads: K/V (zero-filled tail) and Q, all 16B chunks ----
    for (int e = tid; e < KTM * 8; e += 256) {
        int jl = e >> 3;
        int c = e & 7;
        int sz = (jl < numK) ? 16 : 0;
        size_t goff = (size_t)jl * DD + c * 8;
        uint32_t dst = smem_u32 + (uint32_t)(jl * (QK_PITCH * 2) + c * 16);
        cp16z(dst + AOFF_KH, khb + goff, sz);
        cp16z(dst + AOFF_KL, klb + goff, sz);
        cp16z(dst + AOFF_VH, vhb + goff, sz);
        cp16z(dst + AOFF_VL, vlb + goff, sz);
    }
    for (int e = tid; e < QT * 8; e += 256) {
        int qi = e >> 3;
        int c = e & 7;
        size_t goff = (size_t)qi * DD + c * 8;
        uint32_t dst = smem_u32 + (uint32_t)(qi * (QK_PITCH * 2) + c * 16);
        cp16(dst + AOFF_QH, qhb + goff);
        cp16(dst + AOFF_QL, qlb + goff);
    }
    asm volatile("cp.async.commit_group;\n");
    asm volatile("cp.async.wait_group 0;\n");
    __syncthreads();

    // ---- phase 1: scores = Q @ K^T (hi/lo mma) ----
    const int mi = wid & 3;       // q tile (16 rows)
    const int khf = wid >> 2;     // key half (96 keys)
    const int g = lane >> 2;
    const int t2 = (lane & 3) * 2;

    float acc[12][4];
#pragma unroll
    for (int nt = 0; nt < 12; nt++)
#pragma unroll
        for (int r = 0; r < 4; r++) acc[nt][r] = 0.f;

#pragma unroll
    for (int ks = 0; ks < 4; ks++) {
        uint32_t ah[4], al[4];
        int arow = mi * 16 + (lane & 15);
        int acol = ks * 16 + ((lane >> 4) << 3);
        uint32_t aaddr = smem_u32 + AOFF_QH + (uint32_t)(arow * QK_PITCH + acol) * 2;
        ldsm_x4(ah, aaddr);
        ldsm_x4(al, aaddr + (AOFF_QL - AOFF_QH));
#pragma unroll
        for (int nt = 0; nt < 12; nt++) {
            int brow = khf * 96 + nt * 8 + (lane & 7);
            int bcol = ks * 16 + ((lane >> 3) & 1) * 8;
            uint32_t baddr = smem_u32 + AOFF_KH + (uint32_t)(brow * QK_PITCH + bcol) * 2;
            uint32_t bh[2], bl[2];
            ldsm_x2(bh, baddr);
            ldsm_x2(bl, baddr + (AOFF_KL - AOFF_KH));
            mma16816(acc[nt], ah, bh);
            mma16816(acc[nt], ah, bl);
            mma16816(acc[nt], al, bh);
        }
    }

    // ---- mask + partial softmax (per key-half) ----
    const float sm_scale = 0.125f;
    float pmax[2], psum[2];
#pragma unroll
    for (int rp = 0; rp < 2; rp++) {
        int qrow = mi * 16 + g + rp * 8;
        int qg = q0 + qrow;
        int lo = max(0, qg - (WIN - 1)) - kmin;
        int hi = qg - kmin;
        float mx = -1e30f;
#pragma unroll
        for (int nt = 0; nt < 12; nt++) {
#pragma unroll
            for (int c = 0; c < 2; c++) {
                int kl = khf * 96 + nt * 8 + t2 + c;
                float v = acc[nt][rp * 2 + c] * sm_scale;
                v = (kl >= lo && kl <= hi) ? v : -1e30f;
                acc[nt][rp * 2 + c] = v;
                mx = fmaxf(mx, v);
            }
        }
        mx = fmaxf(mx, __shfl_xor_sync(0xffffffffu, mx, 1));
        mx = fmaxf(mx, __shfl_xor_sync(0xffffffffu, mx, 2));
        float sum = 0.f;
#pragma unroll
        for (int nt = 0; nt < 12; nt++) {
#pragma unroll
            for (int c = 0; c < 2; c++) {
                float e = __expf(acc[nt][rp * 2 + c] - mx);
                acc[nt][rp * 2 + c] = e;
                sum += e;
            }
        }
        sum += __shfl_xor_sync(0xffffffffu, sum, 1);
        sum += __shfl_xor_sync(0xffffffffu, sum, 2);
        pmax[rp] = mx;
        psum[rp] = sum;
        if ((lane & 3) == 0) {
            sMax[qrow * 2 + khf] = mx;
            sSum[qrow * 2 + khf] = sum;
        }
    }
    __syncthreads();

    // ---- combine halves, write P (bf16 hi/lo) ----
#pragma unroll
    for (int rp = 0; rp < 2; rp++) {
        int qrow = mi * 16 + g + rp * 8;
        float m0 = sMax[qrow * 2 + 0], m1 = sMax[qrow * 2 + 1];
        float s0 = sSum[qrow * 2 + 0], s1 = sSum[qrow * 2 + 1];
        float M = fmaxf(m0, m1);
        float S = s0 * __expf(m0 - M) + s1 * __expf(m1 - M);
        float factor = __expf(pmax[rp] - M) / S;
#pragma unroll
        for (int nt = 0; nt < 12; nt++) {
            float p0 = acc[nt][rp * 2 + 0] * factor;
            float p1 = acc[nt][rp * 2 + 1] * factor;
            __nv_bfloat16 h0,h1,l0,l1;
            split2(p0,h0,l0); split2(p1,h1,l1);
            int idx = qrow * PV_PITCH + khf * 96 + nt * 8 + t2;
            *(__nv_bfloat162*)&sPh[idx] = __nv_bfloat162{h0,h1};
            *(__nv_bfloat162*)&sPl[idx] = __nv_bfloat162{l0,l1};
        }
    }
    __syncthreads();

    // ---- phase 2: out = P @ V; B fragments via ldmatrix.trans on row-major V
    const int nh = wid >> 2;      // dim half (32 dims)
    float oacc[4][4];
#pragma unroll
    for (int nt = 0; nt < 4; nt++)
#pragma unroll
        for (int r = 0; r < 4; r++) oacc[nt][r] = 0.f;

#pragma unroll
    for (int ks = 0; ks < 12; ks++) {
        uint32_t ah[4], al[4];
        int arow = mi * 16 + (lane & 15);
        int acol = ks * 16 + ((lane >> 4) << 3);
        uint32_t aaddr = smem_u32 + AOFF_PH + (uint32_t)(arow * PV_PITCH + acol) * 2;
        ldsm_x4(ah, aaddr);
        ldsm_x4(al, aaddr + (AOFF_PL - AOFF_PH));
        int brow = ks * 16 + (lane & 15);   // key row in V
#pragma unroll
        for (int nt = 0; nt < 4; nt++) {
            int bcol = nh * 32 + nt * 8;    // dim offset within head
            uint32_t baddr = smem_u32 + AOFF_VH + (uint32_t)(brow * QK_PITCH + bcol) * 2;
            uint32_t bh[2], bl[2];
            ldsm_x2t(bh, baddr);
            ldsm_x2t(bl, baddr + (AOFF_VL - AOFF_VH));
            mma16816(oacc[nt], ah, bh);
            mma16816(oacc[nt], ah, bl);
            mma16816(oacc[nt], al, bh);
        }
    }

    // ---- epilogue: split to bf16 hi/lo, write g_ah/g_al ----
#pragma unroll
    for (int nt = 0; nt < 4; nt++) {
        int col = hoff + nh * 32 + nt * 8 + t2;
        size_t r0 = (size_t)(b * TT + q0 + mi * 16 + g) * DD + col;
        size_t r1 = r0 + (size_t)8 * DD;
        __nv_bfloat16 h0,h1,l0,l1;
        split2(oacc[nt][0],h0,l0); split2(oacc[nt][1],h1,l1);
        *(__nv_bfloat162*)&g_ah[r0] = __nv_bfloat162{h0,h1};
        *(__nv_bfloat162*)&g_al[r0] = __nv_bfloat162{l0,l1};
        split2(oacc[nt][2],h0,l0); split2(oacc[nt][3],h1,l1);
        *(__nv_bfloat162*)&g_ah[r1] = __nv_bfloat162{h0,h1};
        *(__nv_bfloat162*)&g_al[r1] = __nv_bfloat162{l0,l1};
    }
}

// ---------------- launch ----------------------------------------------------
extern "C" void kernel_launch(void* const* d_in, const int* in_sizes, int n_in,
                              void* d_out, int out_size) {
    const float* x  = (const float*)d_in[0];
    const float* Wq = (const float*)d_in[1];
    const float* Wk = (const float*)d_in[2];
    const float* Wv = (const float*)d_in[3];
    const float* Wo = (const float*)d_in[4];
    const float* bo = (const float*)d_in[5];
    float* out = (float*)d_out;

    cudaFuncSetAttribute(attn_kernel, cudaFuncAttributeMaxDynamicSharedMemorySize,
                         ATT_SMEM_BYTES);
    cudaFuncSetAttribute(qkv_mma_kernel, cudaFuncAttributeMaxDynamicSharedMemorySize,
                         G_SMEM_BYTES);
    cudaFuncSetAttribute(out_mma_kernel, cudaFuncAttributeMaxDynamicSharedMemorySize,
                         G_SMEM_BYTES);

    rope_table_kernel<<<(TT * 32 + 255) / 256, 256>>>();

    cvt_x_kernel<<<(BT * DD / 4 + 255) / 256, 256>>>(x);
    cvt_w_all_kernel<<<dim3((DD * DD / 4 + 255) / 256, 4), 256>>>(Wq, Wk, Wv, Wo);

    dim3 gqkv(DD / 128, BT / 128, 3);
    qkv_mma_kernel<<<gqkv, 256, G_SMEM_BYTES>>>();

    rope_apply_kernel<<<(BT * HH * 32 + 255) / 256, 256>>>();

    attn_kernel<<<dim3(TT / QT, HH, BB), 256, ATT_SMEM_BYTES>>>();

    dim3 go(DD / 128, BT / 128, 1);
    out_mma_kernel<<<go, 256, G_SMEM_BYTES>>>(bo, out);
}

// round 9
// speedup vs baseline: 4.8952x; 1.0129x over previous
#include <cuda_runtime.h>
#include <cuda_bf16.h>
#include <math.h>
#include <stdint.h>

// Problem constants
#define BB 2
#define TT 2048
#define DD 1024
#define HH 16
#define DH 64
#define WIN 128
#define BT (BB*TT)          // 4096

// ---------------- scratch (device globals) ----------------------------------
__device__ float g_cos[TT * 32];
__device__ float g_sin[TT * 32];

// bf16 hi/lo operands
__device__ __nv_bfloat16 g_xh[BT * DD];
__device__ __nv_bfloat16 g_xl[BT * DD];
__device__ __nv_bfloat16 g_wh[4][DD * DD];
__device__ __nv_bfloat16 g_wl[4][DD * DD];
__device__ __nv_bfloat16 g_qh[BT * DD];
__device__ __nv_bfloat16 g_ql[BT * DD];
__device__ __nv_bfloat16 g_kh[BT * DD];
__device__ __nv_bfloat16 g_kl[BT * DD];
__device__ __nv_bfloat16 g_vh[BT * DD];
__device__ __nv_bfloat16 g_vl[BT * DD];
__device__ __nv_bfloat16 g_ah[BT * DD];
__device__ __nv_bfloat16 g_al[BT * DD];

// ---------------- RoPE tables ----------------------------------------------
__global__ void rope_table_kernel() {
    int idx = blockIdx.x * blockDim.x + threadIdx.x;
    if (idx >= TT * 32) return;
    int t = idx >> 5;
    int i = idx & 31;
    double inv = exp(-log(10000.0) * (double)(2 * i) / 64.0);
    double a = (double)t * inv;
    g_cos[idx] = (float)cos(a);
    g_sin[idx] = (float)sin(a);
}

// ---------------- fp32 -> bf16 hi/lo split ----------------------------------
__device__ __forceinline__ void split2(float x, __nv_bfloat16& h, __nv_bfloat16& l) {
    h = __float2bfloat16(x);
    l = __float2bfloat16(x - __bfloat162float(h));
}

__global__ void cvt_x_kernel(const float* __restrict__ src) {
    int i = blockIdx.x * blockDim.x + threadIdx.x;
    if (i >= BT * DD / 4) return;
    float4 v = ((const float4*)src)[i];
    __nv_bfloat16 h0,h1,h2,h3,l0,l1,l2,l3;
    split2(v.x,h0,l0); split2(v.y,h1,l1); split2(v.z,h2,l2); split2(v.w,h3,l3);
    ((__nv_bfloat162*)g_xh)[i*2+0] = __nv_bfloat162{h0,h1};
    ((__nv_bfloat162*)g_xh)[i*2+1] = __nv_bfloat162{h2,h3};
    ((__nv_bfloat162*)g_xl)[i*2+0] = __nv_bfloat162{l0,l1};
    ((__nv_bfloat162*)g_xl)[i*2+1] = __nv_bfloat162{l2,l3};
}

__global__ void cvt_w_all_kernel(const float* __restrict__ Wq, const float* __restrict__ Wk,
                                 const float* __restrict__ Wv, const float* __restrict__ Wo) {
    int z = blockIdx.y;
    const float* src = (z == 0) ? Wq : (z == 1) ? Wk : (z == 2) ? Wv : Wo;
    int i = blockIdx.x * blockDim.x + threadIdx.x;
    if (i >= DD * DD / 4) return;
    float4 v = ((const float4*)src)[i];
    __nv_bfloat16 h0,h1,h2,h3,l0,l1,l2,l3;
    split2(v.x,h0,l0); split2(v.y,h1,l1); split2(v.z,h2,l2); split2(v.w,h3,l3);
    ((__nv_bfloat162*)g_wh[z])[i*2+0] = __nv_bfloat162{h0,h1};
    ((__nv_bfloat162*)g_wh[z])[i*2+1] = __nv_bfloat162{h2,h3};
    ((__nv_bfloat162*)g_wl[z])[i*2+0] = __nv_bfloat162{l0,l1};
    ((__nv_bfloat162*)g_wl[z])[i*2+1] = __nv_bfloat162{l2,l3};
}

// ---------------- mma helpers -----------------------------------------------
__device__ __forceinline__ void cp16(uint32_t dst, const void* src) {
    asm volatile("cp.async.cg.shared.global [%0], [%1], 16;\n" :: "r"(dst), "l"(src));
}
__device__ __forceinline__ void cp16z(uint32_t dst, const void* src, int sz) {
    asm volatile("cp.async.cg.shared.global [%0], [%1], 16, %2;\n"
                 :: "r"(dst), "l"(src), "r"(sz));
}
__device__ __forceinline__ void ldsm_x4(uint32_t* r, uint32_t a) {
    asm volatile("ldmatrix.sync.aligned.m8n8.x4.shared.b16 {%0,%1,%2,%3}, [%4];\n"
                 : "=r"(r[0]), "=r"(r[1]), "=r"(r[2]), "=r"(r[3]) : "r"(a));
}
__device__ __forceinline__ void ldsm_x2(uint32_t* r, uint32_t a) {
    asm volatile("ldmatrix.sync.aligned.m8n8.x2.shared.b16 {%0,%1}, [%2];\n"
                 : "=r"(r[0]), "=r"(r[1]) : "r"(a));
}
__device__ __forceinline__ void ldsm_x2t(uint32_t* r, uint32_t a) {
    asm volatile("ldmatrix.sync.aligned.m8n8.x2.trans.shared.b16 {%0,%1}, [%2];\n"
                 : "=r"(r[0]), "=r"(r[1]) : "r"(a));
}
__device__ __forceinline__ void mma16816(float* c, const uint32_t* a, const uint32_t* b) {
    asm volatile("mma.sync.aligned.m16n8k16.row.col.f32.bf16.bf16.f32 "
                 "{%0,%1,%2,%3}, {%4,%5,%6,%7}, {%8,%9}, {%0,%1,%2,%3};\n"
                 : "+f"(c[0]), "+f"(c[1]), "+f"(c[2]), "+f"(c[3])
                 : "r"(a[0]), "r"(a[1]), "r"(a[2]), "r"(a[3]), "r"(b[0]), "r"(b[1]));
}

// ---------------- tensor-core GEMM (hi/lo split, 3-stage, swizzled) ---------
// SMEM per stage: sA[128][64] bf16 (hi cols 0-31, lo cols 32-63), sB same.
// Row = 128 B = 8 chunks of 16 B; phys chunk = logical ^ (row & 7)  -> ldmatrix
// conflict-free with no padding. Stage = 32 KB, 3 stages = 96 KB, 2 CTA/SM.
#define GK_CHUNK 32
#define GS_ARR 16384                 // bytes per array (A or B) per stage
#define GS_STAGE (2 * GS_ARR)        // 32768
#define G_SMEM_BYTES (3 * GS_STAGE)  // 98304

__device__ __forceinline__ void mma_gemm_body(
    const __nv_bfloat16* __restrict__ Ah, const __nv_bfloat16* __restrict__ Al,
    const __nv_bfloat16* __restrict__ Bh, const __nv_bfloat16* __restrict__ Bl,
    float* __restrict__ C, const float* __restrict__ bias,
    __nv_bfloat16* __restrict__ Ch, __nv_bfloat16* __restrict__ Cl)
{
    extern __shared__ char smem_raw[];
    const int tid = threadIdx.x;
    const int lane = tid & 31;
    const int wid = tid >> 5;
    const int bM = blockIdx.y * 128;
    const int bN = blockIdx.x * 128;
    const int wM = (wid >> 2) * 64;
    const int wN = (wid & 3) * 32;

    const uint32_t smem_base = (uint32_t)__cvta_generic_to_shared(smem_raw);

    // loader decomposition: thread covers chunk c8 of rows r0+32*j (j=0..3) x {A,B}
    const int c8 = tid & 7;          // 16B chunk within 128B row
    const int r0 = tid >> 3;         // 0..31

    float acc[4][4][4];
#pragma unroll
    for (int mi = 0; mi < 4; mi++)
#pragma unroll
        for (int ni = 0; ni < 4; ni++)
#pragma unroll
            for (int r = 0; r < 4; r++) acc[mi][ni][r] = 0.f;

    auto issue = [&](int buf, int k0) {
        uint32_t sbase = smem_base + buf * GS_STAGE;
        const int kcol = k0 + (c8 & 3) * 8;
#pragma unroll
        for (int i = 0; i < 8; i++) {
            const int arr = i >> 2;
            const int row = r0 + 32 * (i & 3);
            const __nv_bfloat16* bp;
            int grow;
            if (arr == 0) { bp = (c8 < 4) ? Ah : Al; grow = bM + row; }
            else          { bp = (c8 < 4) ? Bh : Bl; grow = bN + row; }
            uint32_t dst = sbase + arr * GS_ARR + row * 128 +
                           (uint32_t)((c8 ^ (row & 7)) * 16);
            cp16(dst, bp + (size_t)grow * DD + kcol);
        }
        asm volatile("cp.async.commit_group;\n");
    };

    const int NCH = DD / GK_CHUNK;   // 32
    issue(0, 0);
    issue(1, GK_CHUNK);

    for (int c = 0; c < NCH; c++) {
        if (c + 1 < NCH) { asm volatile("cp.async.wait_group 1;\n"); }
        else             { asm volatile("cp.async.wait_group 0;\n"); }
        __syncthreads();
        if (c + 2 < NCH) issue((c + 2) % 3, (c + 2) * GK_CHUNK);

        uint32_t sb = smem_base + (c % 3) * GS_STAGE;
#pragma unroll
        for (int kh = 0; kh < 2; kh++) {
            uint32_t ah[4][4], al[4][4];
            const int chA = kh * 2 + (lane >> 4);
#pragma unroll
            for (int mi = 0; mi < 4; mi++) {
                int row_l = wM + mi * 16 + (lane & 15);
                uint32_t rb = sb + row_l * 128;
                ldsm_x4(ah[mi], rb + (uint32_t)((chA ^ (row_l & 7)) * 16));
                ldsm_x4(al[mi], rb + (uint32_t)(((chA + 4) ^ (row_l & 7)) * 16));
            }
            const int chB = kh * 2 + ((lane >> 3) & 1);
#pragma unroll
            for (int ni = 0; ni < 4; ni++) {
                int row_b = wN + ni * 8 + (lane & 7);
                uint32_t rb = sb + GS_ARR + row_b * 128;
                uint32_t bh[2], bl[2];
                ldsm_x2(bh, rb + (uint32_t)((chB ^ (row_b & 7)) * 16));
                ldsm_x2(bl, rb + (uint32_t)(((chB + 4) ^ (row_b & 7)) * 16));
#pragma unroll
                for (int mi = 0; mi < 4; mi++) {
                    mma16816(acc[mi][ni], ah[mi], bh);
                    mma16816(acc[mi][ni], ah[mi], bl);
                    mma16816(acc[mi][ni], al[mi], bh);
                }
            }
        }
    }

#pragma unroll
    for (int mi = 0; mi < 4; mi++) {
        int m0 = bM + wM + mi * 16 + (lane >> 2);
#pragma unroll
        for (int ni = 0; ni < 4; ni++) {
            int n = bN + wN + ni * 8 + (lane & 3) * 2;
            if (Ch) {
                __nv_bfloat16 h0,h1,l0,l1;
                split2(acc[mi][ni][0],h0,l0); split2(acc[mi][ni][1],h1,l1);
                *(__nv_bfloat162*)&Ch[(size_t)m0 * DD + n] = __nv_bfloat162{h0,h1};
                *(__nv_bfloat162*)&Cl[(size_t)m0 * DD + n] = __nv_bfloat162{l0,l1};
                split2(acc[mi][ni][2],h0,l0); split2(acc[mi][ni][3],h1,l1);
                *(__nv_bfloat162*)&Ch[(size_t)(m0 + 8) * DD + n] = __nv_bfloat162{h0,h1};
                *(__nv_bfloat162*)&Cl[(size_t)(m0 + 8) * DD + n] = __nv_bfloat162{l0,l1};
            } else {
                float b0 = 0.f, b1 = 0.f;
                if (bias) { b0 = bias[n]; b1 = bias[n + 1]; }
                float2 rr0; rr0.x = acc[mi][ni][0] + b0; rr0.y = acc[mi][ni][1] + b1;
                float2 rr1; rr1.x = acc[mi][ni][2] + b0; rr1.y = acc[mi][ni][3] + b1;
                *(float2*)&C[(size_t)m0 * DD + n]       = rr0;
                *(float2*)&C[(size_t)(m0 + 8) * DD + n] = rr1;
            }
        }
    }
}

__global__ void __launch_bounds__(256) qkv_mma_kernel() {
    int z = blockIdx.z;
    __nv_bfloat16* Ch = (z == 0) ? g_qh : (z == 1) ? g_kh : g_vh;
    __nv_bfloat16* Cl = (z == 0) ? g_ql : (z == 1) ? g_kl : g_vl;
    mma_gemm_body(g_xh, g_xl, g_wh[z], g_wl[z], nullptr, nullptr, Ch, Cl);
}

__global__ void __launch_bounds__(256) out_mma_kernel(const float* __restrict__ bo,
                                                      float* __restrict__ out) {
    mma_gemm_body(g_ah, g_al, g_wh[3], g_wl[3], out, bo, nullptr, nullptr);
}

// ---------------- RoPE apply on hi/lo arrays --------------------------------
__global__ void rope_apply_kernel() {
    int idx = blockIdx.x * blockDim.x + threadIdx.x;
    if (idx >= BT * HH * 32) return;
    int bt = idx >> 9;
    int r = idx & 511;
    int h = r >> 5;
    int i = r & 31;
    int t = bt & (TT - 1);
    float c = g_cos[t * 32 + i];
    float s = g_sin[t * 32 + i];
    int base = bt * DD + h * DH + i;

    float q0 = __bfloat162float(g_qh[base]) + __bfloat162float(g_ql[base]);
    float q1 = __bfloat162float(g_qh[base + 32]) + __bfloat162float(g_ql[base + 32]);
    float r0 = q0 * c - q1 * s;
    float r1 = q1 * c + q0 * s;
    __nv_bfloat16 hh, ll;
    split2(r0, hh, ll); g_qh[base] = hh;      g_ql[base] = ll;
    split2(r1, hh, ll); g_qh[base + 32] = hh; g_ql[base + 32] = ll;

    float k0 = __bfloat162float(g_kh[base]) + __bfloat162float(g_kl[base]);
    float k1 = __bfloat162float(g_kh[base + 32]) + __bfloat162float(g_kl[base + 32]);
    r0 = k0 * c - k1 * s;
    r1 = k1 * c + k0 * s;
    split2(r0, hh, ll); g_kh[base] = hh;      g_kl[base] = ll;
    split2(r1, hh, ll); g_kh[base + 32] = hh; g_kl[base + 32] = ll;
}

// ---------------- tensor-core sliding-window attention ----------------------
#define QT 64
#define KTM 192
#define QK_PITCH 72
#define PV_PITCH 200

#define AOFF_QH 0
#define AOFF_QL (AOFF_QH + 64*QK_PITCH*2)
#define AOFF_KH (AOFF_QL + 64*QK_PITCH*2)
#define AOFF_KL (AOFF_KH + 192*QK_PITCH*2)
#define AOFF_VH (AOFF_KL + 192*QK_PITCH*2)
#define AOFF_VL (AOFF_VH + 192*QK_PITCH*2)
#define AOFF_PH (AOFF_VL + 192*QK_PITCH*2)
#define AOFF_PL (AOFF_PH + 64*PV_PITCH*2)
#define AOFF_MAX (AOFF_PL + 64*PV_PITCH*2)
#define AOFF_SUM (AOFF_MAX + 64*2*4)
#define ATT_SMEM_BYTES (AOFF_SUM + 64*2*4)

__global__ void __launch_bounds__(256) attn_kernel() {
    extern __shared__ char sm[];
    const uint32_t smem_u32 = (uint32_t)__cvta_generic_to_shared(sm);

    const int b = blockIdx.z, h = blockIdx.y;
    const int q0 = blockIdx.x * QT;
    const int tid = threadIdx.x;
    const int lane = tid & 31;
    const int wid = tid >> 5;
    const int kmin = max(0, q0 - (WIN - 1));
    const int numK = q0 + QT - kmin;
    const int hoff = h * DH;

    const __nv_bfloat16* khb = g_kh + (size_t)(b * TT + kmin) * DD + hoff;
    const __nv_bfloat16* klb = g_kl + (size_t)(b * TT + kmin) * DD + hoff;
    const __nv_bfloat16* vhb = g_vh + (size_t)(b * TT + kmin) * DD + hoff;
    const __nv_bfloat16* vlb = g_vl + (size_t)(b * TT + kmin) * DD + hoff;
    const __nv_bfloat16* qhb = g_qh + (size_t)(b * TT + q0) * DD + hoff;
    const __nv_bfloat16* qlb = g_ql + (size_t)(b * TT + q0) * DD + hoff;

    __nv_bfloat16* sPh = (__nv_bfloat16*)(sm + AOFF_PH);
    __nv_bfloat16* sPl = (__nv_bfloat16*)(sm + AOFF_PL);
    float* sMax = (float*)(sm + AOFF_MAX);
    float* sSum = (float*)(sm + AOFF_SUM);

    for (int e = tid; e < KTM * 8; e += 256) {
        int jl = e >> 3;
        int c = e & 7;
        int sz = (jl < numK) ? 16 : 0;
        size_t goff = (size_t)jl * DD + c * 8;
        uint32_t dst = smem_u32 + (uint32_t)(jl * (QK_PITCH * 2) + c * 16);
        cp16z(dst + AOFF_KH, khb + goff, sz);
        cp16z(dst + AOFF_KL, klb + goff, sz);
        cp16z(dst + AOFF_VH, vhb + goff, sz);
        cp16z(dst + AOFF_VL, vlb + goff, sz);
    }
    for (int e = tid; e < QT * 8; e += 256) {
        int qi = e >> 3;
        int c = e & 7;
        size_t goff = (size_t)qi * DD + c * 8;
        uint32_t dst = smem_u32 + (uint32_t)(qi * (QK_PITCH * 2) + c * 16);
        cp16(dst + AOFF_QH, qhb + goff);
        cp16(dst + AOFF_QL, qlb + goff);
    }
    asm volatile("cp.async.commit_group;\n");
    asm volatile("cp.async.wait_group 0;\n");
    __syncthreads();

    const int mi = wid & 3;
    const int khf = wid >> 2;
    const int g = lane >> 2;
    const int t2 = (lane & 3) * 2;

    float acc[12][4];
#pragma unroll
    for (int nt = 0; nt < 12; nt++)
#pragma unroll
        for (int r = 0; r < 4; r++) acc[nt][r] = 0.f;

#pragma unroll
    for (int ks = 0; ks < 4; ks++) {
        uint32_t ah[4], al[4];
        int arow = mi * 16 + (lane & 15);
        int acol = ks * 16 + ((lane >> 4) << 3);
        uint32_t aaddr = smem_u32 + AOFF_QH + (uint32_t)(arow * QK_PITCH + acol) * 2;
        ldsm_x4(ah, aaddr);
        ldsm_x4(al, aaddr + (AOFF_QL - AOFF_QH));
#pragma unroll
        for (int nt = 0; nt < 12; nt++) {
            int brow = khf * 96 + nt * 8 + (lane & 7);
            int bcol = ks * 16 + ((lane >> 3) & 1) * 8;
            uint32_t baddr = smem_u32 + AOFF_KH + (uint32_t)(brow * QK_PITCH + bcol) * 2;
            uint32_t bh[2], bl[2];
            ldsm_x2(bh, baddr);
            ldsm_x2(bl, baddr + (AOFF_KL - AOFF_KH));
            mma16816(acc[nt], ah, bh);
            mma16816(acc[nt], ah, bl);
            mma16816(acc[nt], al, bh);
        }
    }

    const float sm_scale = 0.125f;
    float pmax[2];
#pragma unroll
    for (int rp = 0; rp < 2; rp++) {
        int qrow = mi * 16 + g + rp * 8;
        int qg = q0 + qrow;
        int lo = max(0, qg - (WIN - 1)) - kmin;
        int hi = qg - kmin;
        float mx = -1e30f;
#pragma unroll
        for (int nt = 0; nt < 12; nt++) {
#pragma unroll
            for (int c = 0; c < 2; c++) {
                int kl = khf * 96 + nt * 8 + t2 + c;
                float v = acc[nt][rp * 2 + c] * sm_scale;
                v = (kl >= lo && kl <= hi) ? v : -1e30f;
                acc[nt][rp * 2 + c] = v;
                mx = fmaxf(mx, v);
            }
        }
        mx = fmaxf(mx, __shfl_xor_sync(0xffffffffu, mx, 1));
        mx = fmaxf(mx, __shfl_xor_sync(0xffffffffu, mx, 2));
        float sum = 0.f;
#pragma unroll
        for (int nt = 0; nt < 12; nt++) {
#pragma unroll
            for (int c = 0; c < 2; c++) {
                float e = __expf(acc[nt][rp * 2 + c] - mx);
                acc[nt][rp * 2 + c] = e;
                sum += e;
            }
        }
        sum += __shfl_xor_sync(0xffffffffu, sum, 1);
        sum += __shfl_xor_sync(0xffffffffu, sum, 2);
        pmax[rp] = mx;
        if ((lane & 3) == 0) {
            sMax[qrow * 2 + khf] = mx;
            sSum[qrow * 2 + khf] = sum;
        }
    }
    __syncthreads();

#pragma unroll
    for (int rp = 0; rp < 2; rp++) {
        int qrow = mi * 16 + g + rp * 8;
        float m0 = sMax[qrow * 2 + 0], m1 = sMax[qrow * 2 + 1];
        float s0 = sSum[qrow * 2 + 0], s1 = sSum[qrow * 2 + 1];
        float M = fmaxf(m0, m1);
        float S = s0 * __expf(m0 - M) + s1 * __expf(m1 - M);
        float factor = __expf(pmax[rp] - M) / S;
#pragma unroll
        for (int nt = 0; nt < 12; nt++) {
            float p0 = acc[nt][rp * 2 + 0] * factor;
            float p1 = acc[nt][rp * 2 + 1] * factor;
            __nv_bfloat16 h0,h1,l0,l1;
            split2(p0,h0,l0); split2(p1,h1,l1);
            int idx = qrow * PV_PITCH + khf * 96 + nt * 8 + t2;
            *(__nv_bfloat162*)&sPh[idx] = __nv_bfloat162{h0,h1};
            *(__nv_bfloat162*)&sPl[idx] = __nv_bfloat162{l0,l1};
        }
    }
    __syncthreads();

    const int nh = wid >> 2;
    float oacc[4][4];
#pragma unroll
    for (int nt = 0; nt < 4; nt++)
#pragma unroll
        for (int r = 0; r < 4; r++) oacc[nt][r] = 0.f;

#pragma unroll
    for (int ks = 0; ks < 12; ks++) {
        uint32_t ah[4], al[4];
        int arow = mi * 16 + (lane & 15);
        int acol = ks * 16 + ((lane >> 4) << 3);
        uint32_t aaddr = smem_u32 + AOFF_PH + (uint32_t)(arow * PV_PITCH + acol) * 2;
        ldsm_x4(ah, aaddr);
        ldsm_x4(al, aaddr + (AOFF_PL - AOFF_PH));
        int brow = ks * 16 + (lane & 15);
#pragma unroll
        for (int nt = 0; nt < 4; nt++) {
            int bcol = nh * 32 + nt * 8;
            uint32_t baddr = smem_u32 + AOFF_VH + (uint32_t)(brow * QK_PITCH + bcol) * 2;
            uint32_t bh[2], bl[2];
            ldsm_x2t(bh, baddr);
            ldsm_x2t(bl, baddr + (AOFF_VL - AOFF_VH));
            mma16816(oacc[nt], ah, bh);
            mma16816(oacc[nt], ah, bl);
            mma16816(oacc[nt], al, bh);
        }
    }

#pragma unroll
    for (int nt = 0; nt < 4; nt++) {
        int col = hoff + nh * 32 + nt * 8 + t2;
        size_t r0 = (size_t)(b * TT + q0 + mi * 16 + g) * DD + col;
        size_t r1 = r0 + (size_t)8 * DD;
        __nv_bfloat16 h0,h1,l0,l1;
        split2(oacc[nt][0],h0,l0); split2(oacc[nt][1],h1,l1);
        *(__nv_bfloat162*)&g_ah[r0] = __nv_bfloat162{h0,h1};
        *(__nv_bfloat162*)&g_al[r0] = __nv_bfloat162{l0,l1};
        split2(oacc[nt][2],h0,l0); split2(oacc[nt][3],h1,l1);
        *(__nv_bfloat162*)&g_ah[r1] = __nv_bfloat162{h0,h1};
        *(__nv_bfloat162*)&g_al[r1] = __nv_bfloat162{l0,l1};
    }
}

// ---------------- launch ----------------------------------------------------
extern "C" void kernel_launch(void* const* d_in, const int* in_sizes, int n_in,
                              void* d_out, int out_size) {
    const float* x  = (const float*)d_in[0];
    const float* Wq = (const float*)d_in[1];
    const float* Wk = (const float*)d_in[2];
    const float* Wv = (const float*)d_in[3];
    const float* Wo = (const float*)d_in[4];
    const float* bo = (const float*)d_in[5];
    float* out = (float*)d_out;

    cudaFuncSetAttribute(attn_kernel, cudaFuncAttributeMaxDynamicSharedMemorySize,
                         ATT_SMEM_BYTES);
    cudaFuncSetAttribute(qkv_mma_kernel, cudaFuncAttributeMaxDynamicSharedMemorySize,
                         G_SMEM_BYTES);
    cudaFuncSetAttribute(out_mma_kernel, cudaFuncAttributeMaxDynamicSharedMemorySize,
                         G_SMEM_BYTES);

    rope_table_kernel<<<(TT * 32 + 255) / 256, 256>>>();

    cvt_x_kernel<<<(BT * DD / 4 + 255) / 256, 256>>>(x);
    cvt_w_all_kernel<<<dim3((DD * DD / 4 + 255) / 256, 4), 256>>>(Wq, Wk, Wv, Wo);

    dim3 gqkv(DD / 128, BT / 128, 3);
    qkv_mma_kernel<<<gqkv, 256, G_SMEM_BYTES>>>();

    rope_apply_kernel<<<(BT * HH * 32 + 255) / 256, 256>>>();

    attn_kernel<<<dim3(TT / QT, HH, BB), 256, ATT_SMEM_BYTES>>>();

    dim3 go(DD / 128, BT / 128, 1);
    out_mma_kernel<<<go, 256, G_SMEM_BYTES>>>(bo, out);
}

// round 11
// speedup vs baseline: 7.0820x; 1.4467x over previous
#include <cuda_runtime.h>
#include <cuda_fp16.h>
#include <math.h>
#include <stdint.h>

// Problem constants
#define BB 2
#define TT 2048
#define DD 1024
#define HH 16
#define DH 64
#define WIN 128
#define BT (BB*TT)          // 4096

// ---------------- scratch (device globals) ----------------------------------
__device__ float g_cos[TT * 32];
__device__ float g_sin[TT * 32];

// fp16 hi/lo operands (activations: hi+lo = ~21 bits; weights: hi only)
__device__ __half g_xh[BT * DD];
__device__ __half g_xl[BT * DD];
__device__ __half g_wh[4][DD * DD];
__device__ __half g_qh[BT * DD];
__device__ __half g_ql[BT * DD];
__device__ __half g_kh[BT * DD];
__device__ __half g_kl[BT * DD];
__device__ __half g_vh[BT * DD];
__device__ __half g_vl[BT * DD];
__device__ __half g_ah[BT * DD];
__device__ __half g_al[BT * DD];

// ---------------- RoPE tables ----------------------------------------------
__global__ void rope_table_kernel() {
    int idx = blockIdx.x * blockDim.x + threadIdx.x;
    if (idx >= TT * 32) return;
    int t = idx >> 5;
    int i = idx & 31;
    double inv = exp(-log(10000.0) * (double)(2 * i) / 64.0);
    double a = (double)t * inv;
    g_cos[idx] = (float)cos(a);
    g_sin[idx] = (float)sin(a);
}

// ---------------- fp32 -> fp16 hi/lo split ----------------------------------
__device__ __forceinline__ void split2(float x, __half& h, __half& l) {
    h = __float2half_rn(x);
    l = __float2half_rn(x - __half2float(h));
}

__global__ void cvt_x_kernel(const float* __restrict__ src) {
    int i = blockIdx.x * blockDim.x + threadIdx.x;
    if (i >= BT * DD / 4) return;
    float4 v = ((const float4*)src)[i];
    __half h0,h1,h2,h3,l0,l1,l2,l3;
    split2(v.x,h0,l0); split2(v.y,h1,l1); split2(v.z,h2,l2); split2(v.w,h3,l3);
    ((__half2*)g_xh)[i*2+0] = __half2{h0,h1};
    ((__half2*)g_xh)[i*2+1] = __half2{h2,h3};
    ((__half2*)g_xl)[i*2+0] = __half2{l0,l1};
    ((__half2*)g_xl)[i*2+1] = __half2{l2,l3};
}

// weights: hi only (2-product GEMM scheme)
__global__ void cvt_w_all_kernel(const float* __restrict__ Wq, const float* __restrict__ Wk,
                                 const float* __restrict__ Wv, const float* __restrict__ Wo) {
    int z = blockIdx.y;
    const float* src = (z == 0) ? Wq : (z == 1) ? Wk : (z == 2) ? Wv : Wo;
    int i = blockIdx.x * blockDim.x + threadIdx.x;
    if (i >= DD * DD / 4) return;
    float4 v = ((const float4*)src)[i];
    __half h0 = __float2half_rn(v.x), h1 = __float2half_rn(v.y);
    __half h2 = __float2half_rn(v.z), h3 = __float2half_rn(v.w);
    ((__half2*)g_wh[z])[i*2+0] = __half2{h0,h1};
    ((__half2*)g_wh[z])[i*2+1] = __half2{h2,h3};
}

// ---------------- asm helpers -----------------------------------------------
__device__ __forceinline__ void cp16(uint32_t dst, const void* src) {
    asm volatile("cp.async.cg.shared.global [%0], [%1], 16;\n" :: "r"(dst), "l"(src));
}
__device__ __forceinline__ void cp16z(uint32_t dst, const void* src, int sz) {
    asm volatile("cp.async.cg.shared.global [%0], [%1], 16, %2;\n"
                 :: "r"(dst), "l"(src), "r"(sz));
}
__device__ __forceinline__ void ldsm_x4(uint32_t* r, uint32_t a) {
    asm volatile("ldmatrix.sync.aligned.m8n8.x4.shared.b16 {%0,%1,%2,%3}, [%4];\n"
                 : "=r"(r[0]), "=r"(r[1]), "=r"(r[2]), "=r"(r[3]) : "r"(a));
}
__device__ __forceinline__ void ldsm_x2(uint32_t* r, uint32_t a) {
    asm volatile("ldmatrix.sync.aligned.m8n8.x2.shared.b16 {%0,%1}, [%2];\n"
                 : "=r"(r[0]), "=r"(r[1]) : "r"(a));
}
__device__ __forceinline__ void ldsm_x2t(uint32_t* r, uint32_t a) {
    asm volatile("ldmatrix.sync.aligned.m8n8.x2.trans.shared.b16 {%0,%1}, [%2];\n"
                 : "=r"(r[0]), "=r"(r[1]) : "r"(a));
}
__device__ __forceinline__ void mma16816(float* c, const uint32_t* a, const uint32_t* b) {
    asm volatile("mma.sync.aligned.m16n8k16.row.col.f32.f16.f16.f32 "
                 "{%0,%1,%2,%3}, {%4,%5,%6,%7}, {%8,%9}, {%0,%1,%2,%3};\n"
                 : "+f"(c[0]), "+f"(c[1]), "+f"(c[2]), "+f"(c[3])
                 : "r"(a[0]), "r"(a[1]), "r"(a[2]), "r"(a[3]), "r"(b[0]), "r"(b[1]));
}

// ---------------- tensor-core GEMM (fp16, 2-product, 3-stage, swizzled) -----
// C[m,n] = sum_k A[m,k]*B[n,k] (+bias). A = Ah+Al (full precision), B = Bh only.
// SMEM per stage: sA[128][64] f16 (hi cols 0-31, lo cols 32-63), sB[128][64]
// (hi cols 0-31 only; lo half unused). Row = 128 B = 8 chunks of 16 B;
// phys chunk = logical ^ (row & 7). Stage = 32 KB, 3 stages.
#define GK_CHUNK 32
#define GS_ARR 16384
#define GS_STAGE (2 * GS_ARR)
#define G_SMEM_BYTES (3 * GS_STAGE)

__device__ __forceinline__ void mma_gemm_body(
    const __half* __restrict__ Ah_, const __half* __restrict__ Al_,
    const __half* __restrict__ Bh_,
    float* __restrict__ C, const float* __restrict__ bias,
    __half* __restrict__ Ch, __half* __restrict__ Cl)
{
    extern __shared__ char smem_raw[];
    const int tid = threadIdx.x;
    const int lane = tid & 31;
    const int wid = tid >> 5;
    const int bM = blockIdx.y * 128;
    const int bN = blockIdx.x * 128;
    const int wM = (wid >> 2) * 64;
    const int wN = (wid & 3) * 32;

    const uint32_t smem_base = (uint32_t)__cvta_generic_to_shared(smem_raw);

    const int c8 = tid & 7;          // 16B chunk within 128B row
    const int r0 = tid >> 3;         // 0..31

    float acc[4][4][4];
#pragma unroll
    for (int mi = 0; mi < 4; mi++)
#pragma unroll
        for (int ni = 0; ni < 4; ni++)
#pragma unroll
            for (int r = 0; r < 4; r++) acc[mi][ni][r] = 0.f;

    auto issue = [&](int buf, int k0) {
        uint32_t sbase = smem_base + buf * GS_STAGE;
        const int kcol = k0 + (c8 & 3) * 8;
#pragma unroll
        for (int i = 0; i < 8; i++) {
            const int arr = i >> 2;
            if (arr == 1 && c8 >= 4) continue;   // B has no lo half
            const int row = r0 + 32 * (i & 3);
            const __half* bp;
            int grow;
            if (arr == 0) { bp = (c8 < 4) ? Ah_ : Al_; grow = bM + row; }
            else          { bp = Bh_;                  grow = bN + row; }
            uint32_t dst = sbase + arr * GS_ARR + row * 128 +
                           (uint32_t)((c8 ^ (row & 7)) * 16);
            cp16(dst, bp + (size_t)grow * DD + kcol);
        }
        asm volatile("cp.async.commit_group;\n");
    };

    const int NCH = DD / GK_CHUNK;   // 32
    issue(0, 0);
    issue(1, GK_CHUNK);

    for (int c = 0; c < NCH; c++) {
        if (c + 1 < NCH) { asm volatile("cp.async.wait_group 1;\n"); }
        else             { asm volatile("cp.async.wait_group 0;\n"); }
        __syncthreads();
        if (c + 2 < NCH) issue((c + 2) % 3, (c + 2) * GK_CHUNK);

        uint32_t sb = smem_base + (c % 3) * GS_STAGE;
#pragma unroll
        for (int kh = 0; kh < 2; kh++) {
            uint32_t ah[4][4], al[4][4];
            const int chA = kh * 2 + (lane >> 4);
#pragma unroll
            for (int mi = 0; mi < 4; mi++) {
                int row_l = wM + mi * 16 + (lane & 15);
                uint32_t rb = sb + row_l * 128;
                ldsm_x4(ah[mi], rb + (uint32_t)((chA ^ (row_l & 7)) * 16));
                ldsm_x4(al[mi], rb + (uint32_t)(((chA + 4) ^ (row_l & 7)) * 16));
            }
            const int chB = kh * 2 + ((lane >> 3) & 1);
#pragma unroll
            for (int ni = 0; ni < 4; ni++) {
                int row_b = wN + ni * 8 + (lane & 7);
                uint32_t rb = sb + GS_ARR + row_b * 128;
                uint32_t bh[2];
                ldsm_x2(bh, rb + (uint32_t)((chB ^ (row_b & 7)) * 16));
#pragma unroll
                for (int mi = 0; mi < 4; mi++) {
                    mma16816(acc[mi][ni], ah[mi], bh);   // Ah * Bh
                    mma16816(acc[mi][ni], al[mi], bh);   // Al * Bh
                }
            }
        }
    }

#pragma unroll
    for (int mi = 0; mi < 4; mi++) {
        int m0 = bM + wM + mi * 16 + (lane >> 2);
#pragma unroll
        for (int ni = 0; ni < 4; ni++) {
            int n = bN + wN + ni * 8 + (lane & 3) * 2;
            if (Ch) {
                __half h0,h1,l0,l1;
                split2(acc[mi][ni][0],h0,l0); split2(acc[mi][ni][1],h1,l1);
                *(__half2*)&Ch[(size_t)m0 * DD + n] = __half2{h0,h1};
                *(__half2*)&Cl[(size_t)m0 * DD + n] = __half2{l0,l1};
                split2(acc[mi][ni][2],h0,l0); split2(acc[mi][ni][3],h1,l1);
                *(__half2*)&Ch[(size_t)(m0 + 8) * DD + n] = __half2{h0,h1};
                *(__half2*)&Cl[(size_t)(m0 + 8) * DD + n] = __half2{l0,l1};
            } else {
                float b0 = 0.f, b1 = 0.f;
                if (bias) { b0 = bias[n]; b1 = bias[n + 1]; }
                float2 rr0; rr0.x = acc[mi][ni][0] + b0; rr0.y = acc[mi][ni][1] + b1;
                float2 rr1; rr1.x = acc[mi][ni][2] + b0; rr1.y = acc[mi][ni][3] + b1;
                *(float2*)&C[(size_t)m0 * DD + n]       = rr0;
                *(float2*)&C[(size_t)(m0 + 8) * DD + n] = rr1;
            }
        }
    }
}

__global__ void __launch_bounds__(256) qkv_mma_kernel() {
    int z = blockIdx.z;
    __half* Ch = (z == 0) ? g_qh : (z == 1) ? g_kh : g_vh;
    __half* Cl = (z == 0) ? g_ql : (z == 1) ? g_kl : g_vl;
    mma_gemm_body(g_xh, g_xl, g_wh[z], nullptr, nullptr, Ch, Cl);
}

__global__ void __launch_bounds__(256) out_mma_kernel(const float* __restrict__ bo,
                                                      float* __restrict__ out) {
    mma_gemm_body(g_ah, g_al, g_wh[3], out, bo, nullptr, nullptr);
}

// ---------------- RoPE apply on hi/lo arrays --------------------------------
__global__ void rope_apply_kernel() {
    int idx = blockIdx.x * blockDim.x + threadIdx.x;
    if (idx >= BT * HH * 32) return;
    int bt = idx >> 9;
    int r = idx & 511;
    int h = r >> 5;
    int i = r & 31;
    int t = bt & (TT - 1);
    float c = g_cos[t * 32 + i];
    float s = g_sin[t * 32 + i];
    int base = bt * DD + h * DH + i;

    float q0 = __half2float(g_qh[base]) + __half2float(g_ql[base]);
    float q1 = __half2float(g_qh[base + 32]) + __half2float(g_ql[base + 32]);
    float r0 = q0 * c - q1 * s;
    float r1 = q1 * c + q0 * s;
    __half hh, ll;
    split2(r0, hh, ll); g_qh[base] = hh;      g_ql[base] = ll;
    split2(r1, hh, ll); g_qh[base + 32] = hh; g_ql[base + 32] = ll;

    float k0 = __half2float(g_kh[base]) + __half2float(g_kl[base]);
    float k1 = __half2float(g_kh[base + 32]) + __half2float(g_kl[base + 32]);
    r0 = k0 * c - k1 * s;
    r1 = k1 * c + k0 * s;
    split2(r0, hh, ll); g_kh[base] = hh;      g_kl[base] = ll;
    split2(r1, hh, ll); g_kh[base + 32] = hh; g_kl[base + 32] = ll;
}

// ---------------- tensor-core sliding-window attention (fp16, 3-product) ----
#define QT 64
#define KTM 192
#define QK_PITCH 72
#define PV_PITCH 200

#define AOFF_QH 0
#define AOFF_QL (AOFF_QH + 64*QK_PITCH*2)
#define AOFF_KH (AOFF_QL + 64*QK_PITCH*2)
#define AOFF_KL (AOFF_KH + 192*QK_PITCH*2)
#define AOFF_VH (AOFF_KL + 192*QK_PITCH*2)
#define AOFF_VL (AOFF_VH + 192*QK_PITCH*2)
#define AOFF_PH (AOFF_VL + 192*QK_PITCH*2)
#define AOFF_PL (AOFF_PH + 64*PV_PITCH*2)
#define AOFF_MAX (AOFF_PL + 64*PV_PITCH*2)
#define AOFF_SUM (AOFF_MAX + 64*2*4)
#define ATT_SMEM_BYTES (AOFF_SUM + 64*2*4)

__global__ void __launch_bounds__(256) attn_kernel() {
    extern __shared__ char sm[];
    const uint32_t smem_u32 = (uint32_t)__cvta_generic_to_shared(sm);

    const int b = blockIdx.z, h = blockIdx.y;
    const int q0 = blockIdx.x * QT;
    const int tid = threadIdx.x;
    const int lane = tid & 31;
    const int wid = tid >> 5;
    const int kmin = max(0, q0 - (WIN - 1));
    const int numK = q0 + QT - kmin;
    const int hoff = h * DH;

    const __half* khb = g_kh + (size_t)(b * TT + kmin) * DD + hoff;
    const __half* klb = g_kl + (size_t)(b * TT + kmin) * DD + hoff;
    const __half* vhb = g_vh + (size_t)(b * TT + kmin) * DD + hoff;
    const __half* vlb = g_vl + (size_t)(b * TT + kmin) * DD + hoff;
    const __half* qhb = g_qh + (size_t)(b * TT + q0) * DD + hoff;
    const __half* qlb = g_ql + (size_t)(b * TT + q0) * DD + hoff;

    __half* sPh = (__half*)(sm + AOFF_PH);
    __half* sPl = (__half*)(sm + AOFF_PL);
    float* sMax = (float*)(sm + AOFF_MAX);
    float* sSum = (float*)(sm + AOFF_SUM);

    for (int e = tid; e < KTM * 8; e += 256) {
        int jl = e >> 3;
        int c = e & 7;
        int sz = (jl < numK) ? 16 : 0;
        size_t goff = (size_t)jl * DD + c * 8;
        uint32_t dst = smem_u32 + (uint32_t)(jl * (QK_PITCH * 2) + c * 16);
        cp16z(dst + AOFF_KH, khb + goff, sz);
        cp16z(dst + AOFF_KL, klb + goff, sz);
        cp16z(dst + AOFF_VH, vhb + goff, sz);
        cp16z(dst + AOFF_VL, vlb + goff, sz);
    }
    for (int e = tid; e < QT * 8; e += 256) {
        int qi = e >> 3;
        int c = e & 7;
        size_t goff = (size_t)qi * DD + c * 8;
        uint32_t dst = smem_u32 + (uint32_t)(qi * (QK_PITCH * 2) + c * 16);
        cp16(dst + AOFF_QH, qhb + goff);
        cp16(dst + AOFF_QL, qlb + goff);
    }
    asm volatile("cp.async.commit_group;\n");
    asm volatile("cp.async.wait_group 0;\n");
    __syncthreads();

    const int mi = wid & 3;
    const int khf = wid >> 2;
    const int g = lane >> 2;
    const int t2 = (lane & 3) * 2;

    float acc[12][4];
#pragma unroll
    for (int nt = 0; nt < 12; nt++)
#pragma unroll
        for (int r = 0; r < 4; r++) acc[nt][r] = 0.f;

#pragma unroll
    for (int ks = 0; ks < 4; ks++) {
        uint32_t ah[4], al[4];
        int arow = mi * 16 + (lane & 15);
        int acol = ks * 16 + ((lane >> 4) << 3);
        uint32_t aaddr = smem_u32 + AOFF_QH + (uint32_t)(arow * QK_PITCH + acol) * 2;
        ldsm_x4(ah, aaddr);
        ldsm_x4(al, aaddr + (AOFF_QL - AOFF_QH));
#pragma unroll
        for (int nt = 0; nt < 12; nt++) {
            int brow = khf * 96 + nt * 8 + (lane & 7);
            int bcol = ks * 16 + ((lane >> 3) & 1) * 8;
            uint32_t baddr = smem_u32 + AOFF_KH + (uint32_t)(brow * QK_PITCH + bcol) * 2;
            uint32_t bh[2], bl[2];
            ldsm_x2(bh, baddr);
            ldsm_x2(bl, baddr + (AOFF_KL - AOFF_KH));
            mma16816(acc[nt], ah, bh);
            mma16816(acc[nt], ah, bl);
            mma16816(acc[nt], al, bh);
        }
    }

    const float sm_scale = 0.125f;
    float pmax[2];
#pragma unroll
    for (int rp = 0; rp < 2; rp++) {
        int qrow = mi * 16 + g + rp * 8;
        int qg = q0 + qrow;
        int lo = max(0, qg - (WIN - 1)) - kmin;
        int hi = qg - kmin;
        float mx = -1e30f;
#pragma unroll
        for (int nt = 0; nt < 12; nt++) {
#pragma unroll
            for (int c = 0; c < 2; c++) {
                int kl = khf * 96 + nt * 8 + t2 + c;
                float v = acc[nt][rp * 2 + c] * sm_scale;
                v = (kl >= lo && kl <= hi) ? v : -1e30f;
                acc[nt][rp * 2 + c] = v;
                mx = fmaxf(mx, v);
            }
        }
        mx = fmaxf(mx, __shfl_xor_sync(0xffffffffu, mx, 1));
        mx = fmaxf(mx, __shfl_xor_sync(0xffffffffu, mx, 2));
        float sum = 0.f;
#pragma unroll
        for (int nt = 0; nt < 12; nt++) {
#pragma unroll
            for (int c = 0; c < 2; c++) {
                float e = __expf(acc[nt][rp * 2 + c] - mx);
                acc[nt][rp * 2 + c] = e;
                sum += e;
            }
        }
        sum += __shfl_xor_sync(0xffffffffu, sum, 1);
        sum += __shfl_xor_sync(0xffffffffu, sum, 2);
        pmax[rp] = mx;
        if ((lane & 3) == 0) {
            sMax[qrow * 2 + khf] = mx;
            sSum[qrow * 2 + khf] = sum;
        }
    }
    __syncthreads();

#pragma unroll
    for (int rp = 0; rp < 2; rp++) {
        int qrow = mi * 16 + g + rp * 8;
        float m0 = sMax[qrow * 2 + 0], m1 = sMax[qrow * 2 + 1];
        float s0 = sSum[qrow * 2 + 0], s1 = sSum[qrow * 2 + 1];
        float M = fmaxf(m0, m1);
        float S = s0 * __expf(m0 - M) + s1 * __expf(m1 - M);
        float factor = __expf(pmax[rp] - M) / S;
#pragma unroll
        for (int nt = 0; nt < 12; nt++) {
            float p0 = acc[nt][rp * 2 + 0] * factor;
            float p1 = acc[nt][rp * 2 + 1] * factor;
            __half h0,h1,l0,l1;
            split2(p0,h0,l0); split2(p1,h1,l1);
            int idx = qrow * PV_PITCH + khf * 96 + nt * 8 + t2;
            *(__half2*)&sPh[idx] = __half2{h0,h1};
            *(__half2*)&sPl[idx] = __half2{l0,l1};
        }
    }
    __syncthreads();

    const int nh = wid >> 2;
    float oacc[4][4];
#pragma unroll
    for (int nt = 0; nt < 4; nt++)
#pragma unroll
        for (int r = 0; r < 4; r++) oacc[nt][r] = 0.f;

#pragma unroll
    for (int ks = 0; ks < 12; ks++) {
        uint32_t ah[4], al[4];
        int arow = mi * 16 + (lane & 15);
        int acol = ks * 16 + ((lane >> 4) << 3);
        uint32_t aaddr = smem_u32 + AOFF_PH + (uint32_t)(arow * PV_PITCH + acol) * 2;
        ldsm_x4(ah, aaddr);
        ldsm_x4(al, aaddr + (AOFF_PL - AOFF_PH));
        int brow = ks * 16 + (lane & 15);
#pragma unroll
        for (int nt = 0; nt < 4; nt++) {
            int bcol = nh * 32 + nt * 8;
            uint32_t baddr = smem_u32 + AOFF_VH + (uint32_t)(brow * QK_PITCH + bcol) * 2;
            uint32_t bh[2], bl[2];
            ldsm_x2t(bh, baddr);
            ldsm_x2t(bl, baddr + (AOFF_VL - AOFF_VH));
            mma16816(oacc[nt], ah, bh);
            mma16816(oacc[nt], ah, bl);
            mma16816(oacc[nt], al, bh);
        }
    }

#pragma unroll
    for (int nt = 0; nt < 4; nt++) {
        int col = hoff + nh * 32 + nt * 8 + t2;
        size_t r0 = (size_t)(b * TT + q0 + mi * 16 + g) * DD + col;
        size_t r1 = r0 + (size_t)8 * DD;
        __half h0,h1,l0,l1;
        split2(oacc[nt][0],h0,l0); split2(oacc[nt][1],h1,l1);
        *(__half2*)&g_ah[r0] = __half2{h0,h1};
        *(__half2*)&g_al[r0] = __half2{l0,l1};
        split2(oacc[nt][2],h0,l0); split2(oacc[nt][3],h1,l1);
        *(__half2*)&g_ah[r1] = __half2{h0,h1};
        *(__half2*)&g_al[r1] = __half2{l0,l1};
    }
}

// ---------------- launch ----------------------------------------------------
extern "C" void kernel_launch(void* const* d_in, const int* in_sizes, int n_in,
                              void* d_out, int out_size) {
    const float* x  = (const float*)d_in[0];
    const float* Wq = (const float*)d_in[1];
    const float* Wk = (const float*)d_in[2];
    const float* Wv = (const float*)d_in[3];
    const float* Wo = (const float*)d_in[4];
    const float* bo = (const float*)d_in[5];
    float* out = (float*)d_out;

    cudaFuncSetAttribute(attn_kernel, cudaFuncAttributeMaxDynamicSharedMemorySize,
                         ATT_SMEM_BYTES);
    cudaFuncSetAttribute(qkv_mma_kernel, cudaFuncAttributeMaxDynamicSharedMemorySize,
                         G_SMEM_BYTES);
    cudaFuncSetAttribute(out_mma_kernel, cudaFuncAttributeMaxDynamicSharedMemorySize,
                         G_SMEM_BYTES);

    rope_table_kernel<<<(TT * 32 + 255) / 256, 256>>>();

    cvt_x_kernel<<<(BT * DD / 4 + 255) / 256, 256>>>(x);
    cvt_w_all_kernel<<<dim3((DD * DD / 4 + 255) / 256, 4), 256>>>(Wq, Wk, Wv, Wo);

    dim3 gqkv(DD / 128, BT / 128, 3);
    qkv_mma_kernel<<<gqkv, 256, G_SMEM_BYTES>>>();

    rope_apply_kernel<<<(BT * HH * 32 + 255) / 256, 256>>>();

    attn_kernel<<<dim3(TT / QT, HH, BB), 256, ATT_SMEM_BYTES>>>();

    dim3 go(DD / 128, BT / 128, 1);
    out_mma_kernel<<<go, 256, G_SMEM_BYTES>>>(bo, out);
}